// round 1
// baseline (speedup 1.0000x reference)
#include <cuda_runtime.h>
#include <math.h>

#define BB 64
#define TT 1380
#define XD 96
#define HD 192
#define CN 345

// SCALE = 1 / (sqrt(96) * sqrt(192))
#define SCALE_F (1.0f / (9.79795897113271f * 13.856406460551018f))

// Scratch (allocation-free rule: __device__ globals)
__device__ float g_Z[BB * CN * XD];          // 8.5 MB   Z = W2 @ X
__device__ float g_Y[BB * CN * HD];          // 17 MB    Y = SCALE * Z @ W1
__device__ float g_S[(size_t)BB * CN * TT];  // 122 MB   scores / probs

// ---------------------------------------------------------------------------
// Tiled fp32 GEMM, C[m,n] = alpha * sum_k A[m,k] * B[k,n]   (NN)
// A row-major [M,K] (lda), B row-major [K,N] (ldb), C row-major [M,N] (ldc)
// batched over blockIdx.z with element strides (0 = shared operand)
// ---------------------------------------------------------------------------
template <int BM, int BN, int BK, int TM, int TN>
__global__ void gemm_nn(const float* __restrict__ A, const float* __restrict__ B,
                        float* __restrict__ C,
                        int M, int N, int K, int lda, int ldb, int ldc,
                        long sA, long sB, long sC, float alpha) {
    const int b = blockIdx.z;
    A += (long)b * sA; B += (long)b * sB; C += (long)b * sC;

    __shared__ float As[BK][BM + 1];
    __shared__ float Bs[BK][BN];

    const int tid = threadIdx.x;                 // 256 threads
    const int tcols = BN / TN;
    const int tr = tid / tcols, tc = tid % tcols;
    const int m0 = blockIdx.y * BM, n0 = blockIdx.x * BN;

    float acc[TM][TN];
#pragma unroll
    for (int i = 0; i < TM; i++)
#pragma unroll
        for (int j = 0; j < TN; j++) acc[i][j] = 0.0f;

    for (int k0 = 0; k0 < K; k0 += BK) {
        // A tile [BM x BK] -> As[k][m]
        for (int i = tid; i < BM * BK; i += blockDim.x) {
            int m = i / BK, k = i % BK;
            float v = 0.0f;
            if (m0 + m < M && k0 + k < K) v = A[(long)(m0 + m) * lda + (k0 + k)];
            As[k][m] = v;
        }
        // B tile [BK x BN] -> Bs[k][n]
        for (int i = tid; i < BK * BN; i += blockDim.x) {
            int k = i / BN, n = i % BN;
            float v = 0.0f;
            if (n0 + n < N && k0 + k < K) v = B[(long)(k0 + k) * ldb + (n0 + n)];
            Bs[k][n] = v;
        }
        __syncthreads();

#pragma unroll
        for (int k = 0; k < BK; k++) {
            float ar[TM], br[TN];
#pragma unroll
            for (int i = 0; i < TM; i++) ar[i] = As[k][tr * TM + i];
#pragma unroll
            for (int j = 0; j < TN; j++) br[j] = Bs[k][tc * TN + j];
#pragma unroll
            for (int i = 0; i < TM; i++)
#pragma unroll
                for (int j = 0; j < TN; j++) acc[i][j] = fmaf(ar[i], br[j], acc[i][j]);
        }
        __syncthreads();
    }

#pragma unroll
    for (int i = 0; i < TM; i++) {
        int m = m0 + tr * TM + i;
        if (m >= M) continue;
#pragma unroll
        for (int j = 0; j < TN; j++) {
            int n = n0 + tc * TN + j;
            if (n >= N) continue;
            C[(long)m * ldc + n] = alpha * acc[i][j];
        }
    }
}

// ---------------------------------------------------------------------------
// Tiled fp32 GEMM, C[m,n] = alpha * sum_k A[m,k] * B[n,k]   (NT)
// A row-major [M,K] (lda), B row-major [N,K] (ldb)
// ---------------------------------------------------------------------------
template <int BM, int BN, int BK, int TM, int TN>
__global__ void gemm_nt(const float* __restrict__ A, const float* __restrict__ B,
                        float* __restrict__ C,
                        int M, int N, int K, int lda, int ldb, int ldc,
                        long sA, long sB, long sC, float alpha) {
    const int b = blockIdx.z;
    A += (long)b * sA; B += (long)b * sB; C += (long)b * sC;

    __shared__ float As[BK][BM + 1];
    __shared__ float Bs[BK][BN + 1];

    const int tid = threadIdx.x;
    const int tcols = BN / TN;
    const int tr = tid / tcols, tc = tid % tcols;
    const int m0 = blockIdx.y * BM, n0 = blockIdx.x * BN;

    float acc[TM][TN];
#pragma unroll
    for (int i = 0; i < TM; i++)
#pragma unroll
        for (int j = 0; j < TN; j++) acc[i][j] = 0.0f;

    for (int k0 = 0; k0 < K; k0 += BK) {
        for (int i = tid; i < BM * BK; i += blockDim.x) {
            int m = i / BK, k = i % BK;
            float v = 0.0f;
            if (m0 + m < M && k0 + k < K) v = A[(long)(m0 + m) * lda + (k0 + k)];
            As[k][m] = v;
        }
        for (int i = tid; i < BN * BK; i += blockDim.x) {
            int n = i / BK, k = i % BK;
            float v = 0.0f;
            if (n0 + n < N && k0 + k < K) v = B[(long)(n0 + n) * ldb + (k0 + k)];
            Bs[k][n] = v;
        }
        __syncthreads();

#pragma unroll
        for (int k = 0; k < BK; k++) {
            float ar[TM], br[TN];
#pragma unroll
            for (int i = 0; i < TM; i++) ar[i] = As[k][tr * TM + i];
#pragma unroll
            for (int j = 0; j < TN; j++) br[j] = Bs[k][tc * TN + j];
#pragma unroll
            for (int i = 0; i < TM; i++)
#pragma unroll
                for (int j = 0; j < TN; j++) acc[i][j] = fmaf(ar[i], br[j], acc[i][j]);
        }
        __syncthreads();
    }

#pragma unroll
    for (int i = 0; i < TM; i++) {
        int m = m0 + tr * TM + i;
        if (m >= M) continue;
#pragma unroll
        for (int j = 0; j < TN; j++) {
            int n = n0 + tc * TN + j;
            if (n >= N) continue;
            C[(long)m * ldc + n] = alpha * acc[i][j];
        }
    }
}

// ---------------------------------------------------------------------------
// Row softmax over length TT (one block per row, row cached in smem)
// ---------------------------------------------------------------------------
__inline__ __device__ float warpMax(float v) {
#pragma unroll
    for (int o = 16; o > 0; o >>= 1) v = fmaxf(v, __shfl_xor_sync(0xffffffffu, v, o));
    return v;
}
__inline__ __device__ float warpSum(float v) {
#pragma unroll
    for (int o = 16; o > 0; o >>= 1) v += __shfl_xor_sync(0xffffffffu, v, o);
    return v;
}

__global__ void softmax_rows(float* __restrict__ S) {
    const long row = blockIdx.x;           // b*CN + c
    float* p = S + row * TT;
    __shared__ float buf[TT];
    __shared__ float red[8];

    const int tid = threadIdx.x;           // 256
    const int wid = tid >> 5, lid = tid & 31;

    float m = -INFINITY;
    for (int i = tid; i < TT; i += 256) {
        float v = p[i];
        buf[i] = v;
        m = fmaxf(m, v);
    }
    m = warpMax(m);
    if (lid == 0) red[wid] = m;
    __syncthreads();
    if (wid == 0) {
        float v = (lid < 8) ? red[lid] : -INFINITY;
        v = warpMax(v);
        if (lid == 0) red[0] = v;
    }
    __syncthreads();
    m = red[0];
    __syncthreads();

    float s = 0.0f;
    for (int i = tid; i < TT; i += 256) {
        float e = __expf(buf[i] - m);
        buf[i] = e;
        s += e;
    }
    s = warpSum(s);
    if (lid == 0) red[wid] = s;
    __syncthreads();
    if (wid == 0) {
        float v = (lid < 8) ? red[lid] : 0.0f;
        v = warpSum(v);
        if (lid == 0) red[0] = v;
    }
    __syncthreads();
    const float inv = 1.0f / red[0];

    for (int i = tid; i < TT; i += 256) p[i] = buf[i] * inv;
}

// ---------------------------------------------------------------------------
extern "C" void kernel_launch(void* const* d_in, const int* in_sizes, int n_in,
                              void* d_out, int out_size) {
    const float* X  = (const float*)d_in[0];   // [B,T,XD]
    const float* H  = (const float*)d_in[1];   // [B,T,HD]
    const float* W1 = (const float*)d_in[2];   // [XD,HD]
    const float* W2 = (const float*)d_in[3];   // [CN,T]
    float* out = (float*)d_out;                // [B,CN,HD]

    float *Z, *Y, *S;
    cudaGetSymbolAddress((void**)&Z, g_Z);
    cudaGetSymbolAddress((void**)&Y, g_Y);
    cudaGetSymbolAddress((void**)&S, g_S);

    constexpr int BM = 64, BN = 64, BK = 16, TM = 4, TN = 4;
    const dim3 thr(256);

    // K1: Z[b] = W2 @ X[b]      M=CN, N=XD, K=T
    {
        dim3 grid((XD + BN - 1) / BN, (CN + BM - 1) / BM, BB);
        gemm_nn<BM, BN, BK, TM, TN><<<grid, thr>>>(
            W2, X, Z, CN, XD, TT, TT, XD, XD,
            0L, (long)TT * XD, (long)CN * XD, 1.0f);
    }
    // K2: Y[b] = SCALE * Z[b] @ W1     M=CN, N=HD, K=XD
    {
        dim3 grid((HD + BN - 1) / BN, (CN + BM - 1) / BM, BB);
        gemm_nn<BM, BN, BK, TM, TN><<<grid, thr>>>(
            Z, W1, Y, CN, HD, XD, XD, HD, HD,
            (long)CN * XD, 0L, (long)CN * HD, SCALE_F);
    }
    // K3: S[b] = Y[b] @ H[b]^T     M=CN, N=T, K=HD   (NT)
    {
        dim3 grid((TT + BN - 1) / BN, (CN + BM - 1) / BM, BB);
        gemm_nt<BM, BN, BK, TM, TN><<<grid, thr>>>(
            Y, H, S, CN, TT, HD, HD, HD, TT,
            (long)CN * HD, (long)TT * HD, (long)CN * TT, 1.0f);
    }
    // K4: softmax over last dim
    {
        softmax_rows<<<BB * CN, 256>>>(S);
    }
    // K5: out[b] = P[b] @ H[b]     M=CN, N=HD, K=T
    {
        dim3 grid((HD + BN - 1) / BN, (CN + BM - 1) / BM, BB);
        gemm_nn<BM, BN, BK, TM, TN><<<grid, thr>>>(
            S, H, out, CN, HD, TT, TT, HD, HD,
            (long)CN * TT, (long)TT * HD, (long)CN * HD, 1.0f);
    }
}

// round 2
// speedup vs baseline: 1.5213x; 1.5213x over previous
#include <cuda_runtime.h>
#include <math.h>

#define BB 64
#define TT 1380
#define XD 96
#define HD 192
#define CN 345

// SCALE = 1 / (sqrt(96) * sqrt(192))
#define SCALE_F (1.0f / (9.79795897113271f * 13.856406460551018f))

// Scratch (allocation-free rule: __device__ globals)
__device__ float g_Z[BB * CN * XD];          // 8.5 MB   Z = W2 @ X
__device__ float g_Y[BB * CN * HD];          // 17 MB    Y = SCALE * Z @ W1
__device__ float g_S[(size_t)BB * CN * TT];  // 122 MB   scores / probs

// ---------------------------------------------------------------------------
// Double-buffered register-blocked fp32 GEMM.
//   C[m,n] = alpha * sum_k A[m,k] * op(B)           op(B)=B[k,n] (NN) or B[n,k] (NT)
// Batched over blockIdx.z with element strides (0 = shared operand).
// ---------------------------------------------------------------------------
template <int BM, int BN, int BK, int TM, int TN, bool TRANSB>
__global__ void __launch_bounds__((BM / TM) * (BN / TN))
gemm_db(const float* __restrict__ A, const float* __restrict__ B,
        float* __restrict__ C,
        int M, int N, int K, int lda, int ldb, int ldc,
        long sA, long sB, long sC, float alpha) {
    constexpr int THREADS = (BM / TM) * (BN / TN);
    constexpr int NA4 = (BM * BK) / (THREADS * 4);
    constexpr int NB4 = (BN * BK) / (THREADS * 4);
    static_assert(NA4 >= 1 && NB4 >= 1, "tile too small");
    static_assert((BM * BK) % (THREADS * 4) == 0, "A tile not divisible");
    static_assert((BN * BK) % (THREADS * 4) == 0, "B tile not divisible");

    const int b = blockIdx.z;
    A += (long)b * sA; B += (long)b * sB; C += (long)b * sC;

    __shared__ float As[2][BK][BM + 4];
    __shared__ float Bs[2][BK][BN + 4];

    const int tid = threadIdx.x;
    const int m0 = blockIdx.y * BM, n0 = blockIdx.x * BN;
    const int tcols = BN / TN;
    const int tr = tid / tcols, tc = tid % tcols;

    float acc[TM][TN];
#pragma unroll
    for (int i = 0; i < TM; i++)
#pragma unroll
        for (int j = 0; j < TN; j++) acc[i][j] = 0.0f;

    float4 ra[NA4], rb[NB4];

    // ---- global -> register loaders (guarded, zero-filled) ----
    auto loadA = [&](int k0) {
#pragma unroll
        for (int i = 0; i < NA4; i++) {
            int idx = (tid + i * THREADS) * 4;      // over [BM][BK], m-major
            int m = idx / BK, kk = idx % BK;
            int gm = m0 + m, gk = k0 + kk;
            float4 v = make_float4(0.f, 0.f, 0.f, 0.f);
            if (gm < M) {
                if (gk + 3 < K) {
                    v = *(const float4*)&A[(long)gm * lda + gk];
                } else {
                    float* p = (float*)&v;
#pragma unroll
                    for (int j = 0; j < 4; j++)
                        if (gk + j < K) p[j] = A[(long)gm * lda + gk + j];
                }
            }
            ra[i] = v;
        }
    };
    auto storeA = [&](int buf) {
#pragma unroll
        for (int i = 0; i < NA4; i++) {
            int idx = (tid + i * THREADS) * 4;
            int m = idx / BK, kk = idx % BK;
            As[buf][kk + 0][m] = ra[i].x;
            As[buf][kk + 1][m] = ra[i].y;
            As[buf][kk + 2][m] = ra[i].z;
            As[buf][kk + 3][m] = ra[i].w;
        }
    };
    auto loadB = [&](int k0) {
#pragma unroll
        for (int i = 0; i < NB4; i++) {
            float4 v = make_float4(0.f, 0.f, 0.f, 0.f);
            if (!TRANSB) {
                int idx = (tid + i * THREADS) * 4;  // over [BK][BN], k-major
                int kk = idx / BN, n = idx % BN;
                int gk = k0 + kk, gn = n0 + n;
                if (gk < K) {
                    if (gn + 3 < N) {
                        v = *(const float4*)&B[(long)gk * ldb + gn];
                    } else {
                        float* p = (float*)&v;
#pragma unroll
                        for (int j = 0; j < 4; j++)
                            if (gn + j < N) p[j] = B[(long)gk * ldb + gn + j];
                    }
                }
            } else {
                int idx = (tid + i * THREADS) * 4;  // over [BN][BK], n-major
                int n = idx / BK, kk = idx % BK;
                int gn = n0 + n, gk = k0 + kk;
                if (gn < N) {
                    if (gk + 3 < K) {
                        v = *(const float4*)&B[(long)gn * ldb + gk];
                    } else {
                        float* p = (float*)&v;
#pragma unroll
                        for (int j = 0; j < 4; j++)
                            if (gk + j < K) p[j] = B[(long)gn * ldb + gk + j];
                    }
                }
            }
            rb[i] = v;
        }
    };
    auto storeB = [&](int buf) {
#pragma unroll
        for (int i = 0; i < NB4; i++) {
            if (!TRANSB) {
                int idx = (tid + i * THREADS) * 4;
                int kk = idx / BN, n = idx % BN;
                *(float4*)&Bs[buf][kk][n] = rb[i];
            } else {
                int idx = (tid + i * THREADS) * 4;
                int n = idx / BK, kk = idx % BK;
                Bs[buf][kk + 0][n] = rb[i].x;
                Bs[buf][kk + 1][n] = rb[i].y;
                Bs[buf][kk + 2][n] = rb[i].z;
                Bs[buf][kk + 3][n] = rb[i].w;
            }
        }
    };
    auto compute = [&](int buf) {
#pragma unroll
        for (int kk = 0; kk < BK; kk++) {
            float ar[TM], br[TN];
#pragma unroll
            for (int i = 0; i < TM; i++) ar[i] = As[buf][kk][tr * TM + i];
#pragma unroll
            for (int j = 0; j < TN; j++) br[j] = Bs[buf][kk][tc * TN + j];
#pragma unroll
            for (int i = 0; i < TM; i++)
#pragma unroll
                for (int j = 0; j < TN; j++)
                    acc[i][j] = fmaf(ar[i], br[j], acc[i][j]);
        }
    };

    // ---- software-pipelined mainloop ----
    const int nk = (K + BK - 1) / BK;
    loadA(0); loadB(0);
    storeA(0); storeB(0);
    __syncthreads();

    for (int kt = 0; kt < nk; kt++) {
        const int cur = kt & 1;
        if (kt + 1 < nk) { loadA((kt + 1) * BK); loadB((kt + 1) * BK); }
        compute(cur);
        if (kt + 1 < nk) { storeA(cur ^ 1); storeB(cur ^ 1); __syncthreads(); }
    }

    // ---- epilogue ----
#pragma unroll
    for (int i = 0; i < TM; i++) {
        int m = m0 + tr * TM + i;
        if (m >= M) continue;
#pragma unroll
        for (int j = 0; j < TN; j++) {
            int n = n0 + tc * TN + j;
            if (n >= N) continue;
            C[(long)m * ldc + n] = alpha * acc[i][j];
        }
    }
}

// ---------------------------------------------------------------------------
// Row softmax over length TT, vectorized float4 (TT = 1380 = 345 float4)
// ---------------------------------------------------------------------------
__inline__ __device__ float warpMax(float v) {
#pragma unroll
    for (int o = 16; o > 0; o >>= 1) v = fmaxf(v, __shfl_xor_sync(0xffffffffu, v, o));
    return v;
}
__inline__ __device__ float warpSum(float v) {
#pragma unroll
    for (int o = 16; o > 0; o >>= 1) v += __shfl_xor_sync(0xffffffffu, v, o);
    return v;
}

__global__ void softmax_rows_v4(float* __restrict__ S) {
    const long row = blockIdx.x;           // b*CN + c
    float4* p = (float4*)(S + row * (long)TT);
    constexpr int NV = TT / 4;             // 345
    __shared__ float4 buf[NV];
    __shared__ float red[8];

    const int tid = threadIdx.x;           // 256
    const int wid = tid >> 5, lid = tid & 31;

    float m = -INFINITY;
    for (int i = tid; i < NV; i += 256) {
        float4 v = p[i];
        buf[i] = v;
        m = fmaxf(m, fmaxf(fmaxf(v.x, v.y), fmaxf(v.z, v.w)));
    }
    m = warpMax(m);
    if (lid == 0) red[wid] = m;
    __syncthreads();
    if (wid == 0) {
        float v = (lid < 8) ? red[lid] : -INFINITY;
        v = warpMax(v);
        if (lid == 0) red[0] = v;
    }
    __syncthreads();
    m = red[0];
    __syncthreads();

    float s = 0.0f;
    for (int i = tid; i < NV; i += 256) {
        float4 v = buf[i];
        v.x = __expf(v.x - m); v.y = __expf(v.y - m);
        v.z = __expf(v.z - m); v.w = __expf(v.w - m);
        buf[i] = v;
        s += v.x + v.y + v.z + v.w;
    }
    s = warpSum(s);
    if (lid == 0) red[wid] = s;
    __syncthreads();
    if (wid == 0) {
        float v = (lid < 8) ? red[lid] : 0.0f;
        v = warpSum(v);
        if (lid == 0) red[0] = v;
    }
    __syncthreads();
    const float inv = 1.0f / red[0];

    for (int i = tid; i < NV; i += 256) {
        float4 v = buf[i];
        v.x *= inv; v.y *= inv; v.z *= inv; v.w *= inv;
        p[i] = v;
    }
}

// ---------------------------------------------------------------------------
extern "C" void kernel_launch(void* const* d_in, const int* in_sizes, int n_in,
                              void* d_out, int out_size) {
    const float* X  = (const float*)d_in[0];   // [B,T,XD]
    const float* H  = (const float*)d_in[1];   // [B,T,HD]
    const float* W1 = (const float*)d_in[2];   // [XD,HD]
    const float* W2 = (const float*)d_in[3];   // [CN,T]
    float* out = (float*)d_out;                // [B,CN,HD]

    float *Z, *Y, *S;
    cudaGetSymbolAddress((void**)&Z, g_Z);
    cudaGetSymbolAddress((void**)&Y, g_Y);
    cudaGetSymbolAddress((void**)&S, g_S);

    const dim3 thr(256);

    // K1: Z[b] = W2 @ X[b]           M=CN, N=XD, K=TT   (NN, shared A)
    {
        dim3 grid((XD + 63) / 64, (CN + 127) / 128, BB);
        gemm_db<128, 64, 16, 8, 4, false><<<grid, thr>>>(
            W2, X, Z, CN, XD, TT, TT, XD, XD,
            0L, (long)TT * XD, (long)CN * XD, 1.0f);
    }
    // K2: Y[b] = SCALE * Z[b] @ W1   M=CN, N=HD, K=XD   (NN, shared B)
    {
        dim3 grid((HD + 63) / 64, (CN + 127) / 128, BB);
        gemm_db<128, 64, 16, 8, 4, false><<<grid, thr>>>(
            Z, W1, Y, CN, HD, XD, XD, HD, HD,
            (long)CN * XD, 0L, (long)CN * HD, SCALE_F);
    }
    // K3: S[b] = Y[b] @ H[b]^T       M=CN, N=TT, K=HD   (NT)
    {
        dim3 grid((TT + 127) / 128, (CN + 127) / 128, BB);
        gemm_db<128, 128, 16, 8, 8, true><<<grid, thr>>>(
            Y, H, S, CN, TT, HD, HD, HD, TT,
            (long)CN * HD, (long)TT * HD, (long)CN * TT, 1.0f);
    }
    // K4: softmax over last dim
    {
        softmax_rows_v4<<<BB * CN, 256>>>(S);
    }
    // K5: out[b] = P[b] @ H[b]       M=CN, N=HD, K=TT   (NN)
    {
        dim3 grid((HD + 63) / 64, (CN + 127) / 128, BB);
        gemm_db<128, 64, 16, 8, 4, false><<<grid, thr>>>(
            S, H, out, CN, HD, TT, TT, HD, HD,
            (long)CN * TT, (long)TT * HD, (long)CN * HD, 1.0f);
    }
}

// round 5
// speedup vs baseline: 1.8559x; 1.2199x over previous
#include <cuda_runtime.h>
#include <cuda_bf16.h>
#include <cstdint>
#include <math.h>

#define BB 64
#define TT 1380
#define XD 96
#define HD 192
#define CN 345

#define T_PAD 1408           // TT padded to mult of 128
#define XD_PAD 128
#define HD_PAD 192

#define SCALE_F (1.0f / (9.79795897113271f * 13.856406460551018f))

// ---------------- device scratch (allocation-free rule) ----------------
__device__ float g_Z[(long)BB * CN * XD];           // 8.5 MB
__device__ float g_Y[(long)BB * CN * HD];           // 17 MB
__device__ float g_S[(long)BB * CN * TT];           // 122 MB

// bf16 3-plane K-concat buffers.  A-side order: [hi|lo|hi].  B-side order: [hi|hi|lo].
__device__ __align__(16) __nv_bfloat16 g_W2k[(long)CN * 3 * T_PAD];          // A-side
__device__ __align__(16) __nv_bfloat16 g_Xt [(long)BB * XD * 3 * T_PAD];     // B-side
__device__ __align__(16) __nv_bfloat16 g_Zk [(long)BB * CN * 3 * XD_PAD];    // A-side
__device__ __align__(16) __nv_bfloat16 g_W1t[(long)HD * 3 * XD_PAD];         // B-side
__device__ __align__(16) __nv_bfloat16 g_Yk [(long)BB * CN * 3 * HD_PAD];    // A-side
__device__ __align__(16) __nv_bfloat16 g_Hk [(long)BB * TT * 3 * HD_PAD];    // B-side
__device__ __align__(16) __nv_bfloat16 g_Pk [(long)BB * CN * 3 * T_PAD];     // A-side
__device__ __align__(16) __nv_bfloat16 g_Ht [(long)BB * HD * 3 * T_PAD];     // B-side

// ---------------- mma helpers (plain PTX, sm_80-class) ----------------
__device__ __forceinline__ uint32_t smem_u32(const void* p) {
    uint32_t a;
    asm("{ .reg .u64 t; cvta.to.shared.u64 t, %1; cvt.u32.u64 %0, t; }" : "=r"(a) : "l"(p));
    return a;
}
__device__ __forceinline__ void ldm_x4(uint32_t addr, uint32_t* r) {
    asm volatile("ldmatrix.sync.aligned.m8n8.x4.shared.b16 {%0,%1,%2,%3}, [%4];"
                 : "=r"(r[0]), "=r"(r[1]), "=r"(r[2]), "=r"(r[3]) : "r"(addr));
}
__device__ __forceinline__ void mma16816(float* c, const uint32_t* a, const uint32_t* b) {
    asm volatile("mma.sync.aligned.m16n8k16.row.col.f32.bf16.bf16.f32 "
                 "{%0,%1,%2,%3}, {%4,%5,%6,%7}, {%8,%9}, {%0,%1,%2,%3};"
                 : "+f"(c[0]), "+f"(c[1]), "+f"(c[2]), "+f"(c[3])
                 : "r"(a[0]), "r"(a[1]), "r"(a[2]), "r"(a[3]), "r"(b[0]), "r"(b[1]));
}

// ---------------- warp-mma batched GEMM:  C[m,n] = alpha * sum_k A[m,k]*B[n,k] ----
// Block tile 128x128, 8 warps (32x64 each), BK=32, double-buffered smem.
#define LDS_PAD 40

__global__ void __launch_bounds__(256, 2)
gemm_mma(const __nv_bfloat16* __restrict__ A, const __nv_bfloat16* __restrict__ B,
         float* __restrict__ C, int M, int N, int Kp, int lda, int ldb, int ldc,
         long sA, long sB, long sC, float alpha) {
    __shared__ __nv_bfloat16 As[2][128][LDS_PAD];
    __shared__ __nv_bfloat16 Bs[2][128][LDS_PAD];

    const int tid = threadIdx.x;
    const int wid = tid >> 5, lane = tid & 31;
    const int wm = wid & 3, wn = wid >> 2;     // 4 (m) x 2 (n) warps
    const int bz = blockIdx.z;
    const __nv_bfloat16* Ab = A + (long)bz * sA;
    const __nv_bfloat16* Bb = B + (long)bz * sB;
    float* Cb = C + (long)bz * sC;
    const int m0 = blockIdx.y * 128, n0 = blockIdx.x * 128;

    float acc[2][8][4];
#pragma unroll
    for (int i = 0; i < 2; i++)
#pragma unroll
        for (int j = 0; j < 8; j++)
#pragma unroll
            for (int q = 0; q < 4; q++) acc[i][j][q] = 0.0f;

    // ldmatrix lane address components
    const int la16 = lane & 15, lhi = lane >> 4;          // A: rows, k-half
    const int bn = (lane & 7) + ((lane >> 4) & 1) * 8;    // B: row within 16-group
    const int bk = ((lane >> 3) & 1) * 8;                 // B: k-half

    const int lrow = tid >> 2, lch = tid & 3;             // loader: 2x(row,chunk16B)

    uint4 ra[2], rb[2];

#define GLOAD(dst, src, row0, rowMax, ld, k0)                                   \
    {                                                                           \
        _Pragma("unroll")                                                       \
        for (int i_ = 0; i_ < 2; i_++) {                                        \
            int row_ = lrow + i_ * 64;                                          \
            long gr_ = (long)(row0) + row_;                                     \
            uint4 v_ = make_uint4(0u, 0u, 0u, 0u);                              \
            if (gr_ < (rowMax)) v_ = *(const uint4*)((src) + gr_ * (long)(ld) + (k0) + lch * 8); \
            dst[i_] = v_;                                                       \
        }                                                                       \
    }
#define SSTORE(Sb, vreg)                                                        \
    {                                                                           \
        _Pragma("unroll")                                                       \
        for (int i_ = 0; i_ < 2; i_++)                                          \
            *(uint4*)&Sb[lrow + i_ * 64][lch * 8] = vreg[i_];                   \
    }
#define COMPUTE(bufA, bufB)                                                     \
    {                                                                           \
        _Pragma("unroll")                                                       \
        for (int ks_ = 0; ks_ < 2; ks_++) {                                     \
            uint32_t af_[2][4], bf_[4][4];                                      \
            _Pragma("unroll")                                                   \
            for (int mi_ = 0; mi_ < 2; mi_++)                                   \
                ldm_x4(smem_u32(&bufA[wm * 32 + mi_ * 16 + la16][ks_ * 16 + lhi * 8]), af_[mi_]); \
            _Pragma("unroll")                                                   \
            for (int p_ = 0; p_ < 4; p_++)                                      \
                ldm_x4(smem_u32(&bufB[wn * 64 + p_ * 16 + bn][ks_ * 16 + bk]), bf_[p_]); \
            _Pragma("unroll")                                                   \
            for (int mi_ = 0; mi_ < 2; mi_++)                                   \
                _Pragma("unroll")                                               \
                for (int nj_ = 0; nj_ < 8; nj_++)                               \
                    mma16816(acc[mi_][nj_], af_[mi_], bf_[nj_ >> 1] + (nj_ & 1) * 2); \
        }                                                                       \
    }

    const int nk = Kp >> 5;   // BK = 32
    GLOAD(ra, Ab, m0, M, lda, 0);
    GLOAD(rb, Bb, n0, N, ldb, 0);
    SSTORE(As[0], ra);
    SSTORE(Bs[0], rb);
    __syncthreads();

    for (int kt = 0; kt < nk; kt++) {
        const int cur = kt & 1;
        if (kt + 1 < nk) {
            GLOAD(ra, Ab, m0, M, lda, (kt + 1) * 32);
            GLOAD(rb, Bb, n0, N, ldb, (kt + 1) * 32);
        }
        COMPUTE(As[cur], Bs[cur]);
        if (kt + 1 < nk) {
            __syncthreads();
            SSTORE(As[cur ^ 1], ra);
            SSTORE(Bs[cur ^ 1], rb);
            __syncthreads();
        }
    }

    // epilogue
    const int gid = lane >> 2, tig = lane & 3;
#pragma unroll
    for (int mi = 0; mi < 2; mi++) {
#pragma unroll
        for (int nj = 0; nj < 8; nj++) {
            int r = m0 + wm * 32 + mi * 16 + gid;
            int c = n0 + wn * 64 + nj * 8 + tig * 2;
            if (c < N) {
                if (r < M) {
                    float2 v = make_float2(acc[mi][nj][0] * alpha, acc[mi][nj][1] * alpha);
                    *(float2*)&Cb[(long)r * ldc + c] = v;
                }
                if (r + 8 < M) {
                    float2 v = make_float2(acc[mi][nj][2] * alpha, acc[mi][nj][3] * alpha);
                    *(float2*)&Cb[(long)(r + 8) * ldc + c] = v;
                }
            }
        }
    }
#undef GLOAD
#undef SSTORE
#undef COMPUTE
}

// ---------------- converts ----------------
// 3-plane split along K.  ASIDE: [hi|lo|hi].  B-side: [hi|hi|lo].
template <bool ASIDE>
__global__ void split3(const float* __restrict__ in, __nv_bfloat16* __restrict__ out,
                       long rows, int Kin, int Kpad) {
    long total = rows * (long)Kpad;
    for (long idx = blockIdx.x * (long)blockDim.x + threadIdx.x; idx < total;
         idx += (long)gridDim.x * blockDim.x) {
        long row = idx / Kpad;
        int k = (int)(idx - row * Kpad);
        float v = (k < Kin) ? in[row * (long)Kin + k] : 0.0f;
        __nv_bfloat16 hi = __float2bfloat16(v);
        __nv_bfloat16 lo = __float2bfloat16(v - __bfloat162float(hi));
        __nv_bfloat16* o = out + row * (long)(3 * Kpad);
        o[k] = hi;
        if (ASIDE) {
            o[Kpad + k] = lo;
            o[2 * Kpad + k] = hi;
        } else {
            o[Kpad + k] = hi;
            o[2 * Kpad + k] = lo;
        }
    }
}

// transpose + 3-plane split: in [B][R][Cc] fp32 -> out [B][Cc][3*Rpad] bf16 (B-side order)
__global__ void tsplit3(const float* __restrict__ in, __nv_bfloat16* __restrict__ out,
                        int R, int Cc, int Rpad, long sIn, long sOut) {
    __shared__ float t[32][33];
    const int b = blockIdx.z;
    const float* ip = in + (long)b * sIn;
    __nv_bfloat16* op = out + (long)b * sOut;
    const int r0 = blockIdx.x * 32, c0 = blockIdx.y * 32;
    const int tx = threadIdx.x, ty = threadIdx.y;    // 32x8
    for (int i = ty; i < 32; i += 8) {
        int r = r0 + i, c = c0 + tx;
        t[i][tx] = (r < R && c < Cc) ? ip[(long)r * Cc + c] : 0.0f;
    }
    __syncthreads();
    for (int i = ty; i < 32; i += 8) {
        int c = c0 + i, r = r0 + tx;
        if (c < Cc && r < Rpad) {
            float v = t[tx][i];
            __nv_bfloat16 hi = __float2bfloat16(v);
            __nv_bfloat16 lo = __float2bfloat16(v - __bfloat162float(hi));
            __nv_bfloat16* o = op + (long)c * (3 * Rpad);
            o[r] = hi;
            o[Rpad + r] = hi;       // B-side: plane1 = hi
            o[2 * Rpad + r] = lo;   // B-side: plane2 = lo
        }
    }
}

// ---------------- softmax ----------------
__inline__ __device__ float warpMax(float v) {
#pragma unroll
    for (int o = 16; o > 0; o >>= 1) v = fmaxf(v, __shfl_xor_sync(0xffffffffu, v, o));
    return v;
}
__inline__ __device__ float warpSum(float v) {
#pragma unroll
    for (int o = 16; o > 0; o >>= 1) v += __shfl_xor_sync(0xffffffffu, v, o);
    return v;
}
__global__ void softmax_rows_v4(float* __restrict__ S) {
    const long row = blockIdx.x;
    float4* p = (float4*)(S + row * (long)TT);
    constexpr int NV = TT / 4;
    __shared__ float4 buf[NV];
    __shared__ float red[8];
    const int tid = threadIdx.x;
    const int wid = tid >> 5, lid = tid & 31;

    float m = -INFINITY;
    for (int i = tid; i < NV; i += 256) {
        float4 v = p[i];
        buf[i] = v;
        m = fmaxf(m, fmaxf(fmaxf(v.x, v.y), fmaxf(v.z, v.w)));
    }
    m = warpMax(m);
    if (lid == 0) red[wid] = m;
    __syncthreads();
    if (wid == 0) {
        float v = (lid < 8) ? red[lid] : -INFINITY;
        v = warpMax(v);
        if (lid == 0) red[0] = v;
    }
    __syncthreads();
    m = red[0];
    __syncthreads();

    float s = 0.0f;
    for (int i = tid; i < NV; i += 256) {
        float4 v = buf[i];
        v.x = __expf(v.x - m); v.y = __expf(v.y - m);
        v.z = __expf(v.z - m); v.w = __expf(v.w - m);
        buf[i] = v;
        s += v.x + v.y + v.z + v.w;
    }
    s = warpSum(s);
    if (lid == 0) red[wid] = s;
    __syncthreads();
    if (wid == 0) {
        float v = (lid < 8) ? red[lid] : 0.0f;
        v = warpSum(v);
        if (lid == 0) red[0] = v;
    }
    __syncthreads();
    const float inv = 1.0f / red[0];
    for (int i = tid; i < NV; i += 256) {
        float4 v = buf[i];
        v.x *= inv; v.y *= inv; v.z *= inv; v.w *= inv;
        p[i] = v;
    }
}

// ---------------- driver ----------------
extern "C" void kernel_launch(void* const* d_in, const int* in_sizes, int n_in,
                              void* d_out, int out_size) {
    const float* X  = (const float*)d_in[0];   // [B,T,XD]
    const float* H  = (const float*)d_in[1];   // [B,T,HD]
    const float* W1 = (const float*)d_in[2];   // [XD,HD]
    const float* W2 = (const float*)d_in[3];   // [CN,T]
    float* out = (float*)d_out;                // [B,CN,HD]

    float *Z, *Y, *S;
    __nv_bfloat16 *W2k, *Xt, *Zk, *W1t, *Yk, *Hk, *Pk, *Ht;
    cudaGetSymbolAddress((void**)&Z, g_Z);
    cudaGetSymbolAddress((void**)&Y, g_Y);
    cudaGetSymbolAddress((void**)&S, g_S);
    cudaGetSymbolAddress((void**)&W2k, g_W2k);
    cudaGetSymbolAddress((void**)&Xt, g_Xt);
    cudaGetSymbolAddress((void**)&Zk, g_Zk);
    cudaGetSymbolAddress((void**)&W1t, g_W1t);
    cudaGetSymbolAddress((void**)&Yk, g_Yk);
    cudaGetSymbolAddress((void**)&Hk, g_Hk);
    cudaGetSymbolAddress((void**)&Pk, g_Pk);
    cudaGetSymbolAddress((void**)&Ht, g_Ht);

    const dim3 tb(32, 8);

    // prep: X^T split (B-side), W2 split (A-side)
    tsplit3<<<dim3(T_PAD / 32, XD / 32, BB), tb>>>(X, Xt, TT, XD, T_PAD,
                                                   (long)TT * XD, (long)XD * 3 * T_PAD);
    split3<true><<<1024, 256>>>(W2, W2k, CN, TT, T_PAD);

    // K1: Z[b] = W2 @ X[b]        M=345 N=96 K'=4224
    gemm_mma<<<dim3(1, 3, BB), 256>>>(W2k, Xt, Z, CN, XD, 3 * T_PAD,
                                      3 * T_PAD, 3 * T_PAD, XD,
                                      0L, (long)XD * 3 * T_PAD, (long)CN * XD, 1.0f);

    // prep: Z split (A-side), W1^T split (B-side)
    split3<true><<<1024, 256>>>(Z, Zk, (long)BB * CN, XD, XD_PAD);
    tsplit3<<<dim3(XD_PAD / 32, HD / 32, 1), tb>>>(W1, W1t, XD, HD, XD_PAD, 0L, 0L);

    // K2: Y[b] = SCALE * Z[b] @ W1    M=345 N=192 K'=384
    gemm_mma<<<dim3(2, 3, BB), 256>>>(Zk, W1t, Y, CN, HD, 3 * XD_PAD,
                                      3 * XD_PAD, 3 * XD_PAD, HD,
                                      (long)CN * 3 * XD_PAD, 0L, (long)CN * HD, SCALE_F);

    // prep: Y split (A-side), H split (B-side, K-major natural)
    split3<true><<<1024, 256>>>(Y, Yk, (long)BB * CN, HD, HD_PAD);
    split3<false><<<2048, 256>>>(H, Hk, (long)BB * TT, HD, HD_PAD);

    // K3: S[b] = Y[b] @ H[b]^T    M=345 N=1380 K'=576
    gemm_mma<<<dim3(11, 3, BB), 256>>>(Yk, Hk, S, CN, TT, 3 * HD_PAD,
                                       3 * HD_PAD, 3 * HD_PAD, TT,
                                       (long)CN * 3 * HD_PAD, (long)TT * 3 * HD_PAD,
                                       (long)CN * TT, 1.0f);

    // softmax
    softmax_rows_v4<<<BB * CN, 256>>>(S);

    // prep: P split (A-side), H^T split (B-side)
    split3<true><<<2048, 256>>>(S, Pk, (long)BB * CN, TT, T_PAD);
    tsplit3<<<dim3(T_PAD / 32, HD / 32, BB), tb>>>(H, Ht, TT, HD, T_PAD,
                                                   (long)TT * HD, (long)HD * 3 * T_PAD);

    // K5: out[b] = P[b] @ H[b]    M=345 N=192 K'=4224
    gemm_mma<<<dim3(2, 3, BB), 256>>>(Pk, Ht, out, CN, HD, 3 * T_PAD,
                                      3 * T_PAD, 3 * T_PAD, HD,
                                      (long)CN * 3 * T_PAD, (long)HD * 3 * T_PAD,
                                      (long)CN * HD, 1.0f);
}

// round 6
// speedup vs baseline: 2.4299x; 1.3093x over previous
#include <cuda_runtime.h>
#include <cuda_bf16.h>
#include <cstdint>
#include <math.h>

#define BB 64
#define TT 1380
#define XD 96
#define HD 192
#define CN 345

#define T_PAD 1408           // TT padded to mult of 128
#define XD_PAD 128
#define HD_PAD 192

#define SCALE_F (1.0f / (9.79795897113271f * 13.856406460551018f))

// ---------------- device scratch (allocation-free rule) ----------------
__device__ float g_Z[(long)BB * CN * XD];
__device__ float g_Y[(long)BB * CN * HD];
__device__ float g_S[(long)BB * CN * TT];

// bf16 3-plane K-concat buffers.  A-side order: [hi|lo|hi].  B-side order: [hi|hi|lo].
__device__ __align__(16) __nv_bfloat16 g_W2k[(long)CN * 3 * T_PAD];          // A-side
__device__ __align__(16) __nv_bfloat16 g_Xt [(long)BB * XD * 3 * T_PAD];     // B-side
__device__ __align__(16) __nv_bfloat16 g_Zk [(long)BB * CN * 3 * XD_PAD];    // A-side
__device__ __align__(16) __nv_bfloat16 g_W1t[(long)HD * 3 * XD_PAD];         // B-side
__device__ __align__(16) __nv_bfloat16 g_Yk [(long)BB * CN * 3 * HD_PAD];    // A-side
__device__ __align__(16) __nv_bfloat16 g_Hk [(long)BB * TT * 3 * HD_PAD];    // B-side
__device__ __align__(16) __nv_bfloat16 g_Pk [(long)BB * CN * 3 * T_PAD];     // A-side
__device__ __align__(16) __nv_bfloat16 g_Ht [(long)BB * HD * 3 * T_PAD];     // B-side

// ---------------- PTX helpers (sm_80-class, safe at compute_103) ----------------
__device__ __forceinline__ uint32_t smem_u32(const void* p) {
    uint32_t a;
    asm("{ .reg .u64 t; cvta.to.shared.u64 t, %1; cvt.u32.u64 %0, t; }" : "=r"(a) : "l"(p));
    return a;
}
__device__ __forceinline__ void ldm_x4(uint32_t addr, uint32_t* r) {
    asm volatile("ldmatrix.sync.aligned.m8n8.x4.shared.b16 {%0,%1,%2,%3}, [%4];"
                 : "=r"(r[0]), "=r"(r[1]), "=r"(r[2]), "=r"(r[3]) : "r"(addr));
}
__device__ __forceinline__ void mma16816(float* c, const uint32_t* a, const uint32_t* b) {
    asm volatile("mma.sync.aligned.m16n8k16.row.col.f32.bf16.bf16.f32 "
                 "{%0,%1,%2,%3}, {%4,%5,%6,%7}, {%8,%9}, {%0,%1,%2,%3};"
                 : "+f"(c[0]), "+f"(c[1]), "+f"(c[2]), "+f"(c[3])
                 : "r"(a[0]), "r"(a[1]), "r"(a[2]), "r"(a[3]), "r"(b[0]), "r"(b[1]));
}
__device__ __forceinline__ void cp16(uint32_t dst, const void* src, int sz) {
    asm volatile("cp.async.cg.shared.global [%0], [%1], 16, %2;" :: "r"(dst), "l"(src), "r"(sz));
}

// ---------------- cp.async 3-stage pipelined GEMM:  C[m,n] = alpha*sum_k A[m,k]*B[n,k] ----
// BM=128, BK=32, template BN (128 or 96). 8 warps: 4(m) x 2(n), warp tile 32 x BN/2.
template <int BN>
__global__ void __launch_bounds__(256)
gemm_ca(const __nv_bfloat16* __restrict__ A, const __nv_bfloat16* __restrict__ B,
        float* __restrict__ C, int M, int N, int Kp, int lda, int ldb, int ldc,
        long sA, long sB, long sC, float alpha) {
    constexpr int BM = 128, BK = 32, STAGES = 3, PAD = 40;
    constexpr int WN = BN / 2, NP = WN / 16, NJ = WN / 8;
    constexpr int AE = BM * PAD, BE = BN * PAD, SE = AE + BE;
    constexpr int BCH = BN * 4;                 // B 16B-chunks per stage
    extern __shared__ __nv_bfloat16 sm[];

    const int tid = threadIdx.x;
    const int wid = tid >> 5, lane = tid & 31;
    const int wm = wid & 3, wn = wid >> 2;
    const int bz = blockIdx.z;
    const __nv_bfloat16* Ab = A + (long)bz * sA;
    const __nv_bfloat16* Bb = B + (long)bz * sB;
    float* Cb = C + (long)bz * sC;
    const int m0 = blockIdx.y * BM, n0 = blockIdx.x * BN;

    float acc[2][NJ][4];
#pragma unroll
    for (int i = 0; i < 2; i++)
#pragma unroll
        for (int j = 0; j < NJ; j++)
#pragma unroll
            for (int q = 0; q < 4; q++) acc[i][j][q] = 0.0f;

    const int la16 = lane & 15, lhi = lane >> 4;
    const int bn = (lane & 7) + ((lane >> 4) & 1) * 8;
    const int bk = ((lane >> 3) & 1) * 8;

    auto load_stage = [&](int s, int kt) {
        __nv_bfloat16* as = sm + s * SE;
        __nv_bfloat16* bs = sm + s * SE + AE;
        const long k0 = (long)kt * BK;
#pragma unroll
        for (int i = 0; i < 2; i++) {               // A: 512 chunks, 2/thread
            int c = tid + i * 256;
            int row = c >> 2, col = c & 3;
            long gr = m0 + row;
            int ok = gr < M;
            const __nv_bfloat16* gp = Ab + (ok ? gr : 0) * (long)lda + k0 + col * 8;
            cp16(smem_u32(as + row * PAD + col * 8), gp, ok ? 16 : 0);
        }
#pragma unroll
        for (int i = 0; i < (BCH + 255) / 256; i++) {
            int c = tid + i * 256;
            if (c < BCH) {
                int row = c >> 2, col = c & 3;
                long gr = n0 + row;
                int ok = gr < N;
                const __nv_bfloat16* gp = Bb + (ok ? gr : 0) * (long)ldb + k0 + col * 8;
                cp16(smem_u32(bs + row * PAD + col * 8), gp, ok ? 16 : 0);
            }
        }
        asm volatile("cp.async.commit_group;");
    };

    auto compute = [&](int s) {
        __nv_bfloat16* as = sm + s * SE;
        __nv_bfloat16* bs = sm + s * SE + AE;
#pragma unroll
        for (int ks = 0; ks < 2; ks++) {
            uint32_t af[2][4], bf[NP][4];
#pragma unroll
            for (int mi = 0; mi < 2; mi++)
                ldm_x4(smem_u32(as + (wm * 32 + mi * 16 + la16) * PAD + ks * 16 + lhi * 8), af[mi]);
#pragma unroll
            for (int p = 0; p < NP; p++)
                ldm_x4(smem_u32(bs + (wn * WN + p * 16 + bn) * PAD + ks * 16 + bk), bf[p]);
#pragma unroll
            for (int mi = 0; mi < 2; mi++)
#pragma unroll
                for (int nj = 0; nj < NJ; nj++)
                    mma16816(acc[mi][nj], af[mi], bf[nj >> 1] + (nj & 1) * 2);
        }
    };

    const int nk = Kp / BK;
    load_stage(0, 0);
    load_stage(1, 1);

    for (int kt = 0; kt < nk; kt++) {
        asm volatile("cp.async.wait_group %0;" :: "n"(STAGES - 2));
        __syncthreads();
        if (kt + STAGES - 1 < nk) load_stage((kt + STAGES - 1) % STAGES, kt + STAGES - 1);
        compute(kt % STAGES);
    }

    // epilogue
    const int gid = lane >> 2, tig = lane & 3;
#pragma unroll
    for (int mi = 0; mi < 2; mi++) {
#pragma unroll
        for (int nj = 0; nj < NJ; nj++) {
            int r = m0 + wm * 32 + mi * 16 + gid;
            int c = n0 + wn * WN + nj * 8 + tig * 2;
            if (c < N) {
                if (r < M) {
                    float2 v = make_float2(acc[mi][nj][0] * alpha, acc[mi][nj][1] * alpha);
                    *(float2*)&Cb[(long)r * ldc + c] = v;
                }
                if (r + 8 < M) {
                    float2 v = make_float2(acc[mi][nj][2] * alpha, acc[mi][nj][3] * alpha);
                    *(float2*)&Cb[(long)(r + 8) * ldc + c] = v;
                }
            }
        }
    }
}

// ---------------- converts ----------------
template <bool ASIDE>
__global__ void split3(const float* __restrict__ in, __nv_bfloat16* __restrict__ out,
                       long rows, int Kin, int Kpad) {
    long total = rows * (long)Kpad;
    for (long idx = blockIdx.x * (long)blockDim.x + threadIdx.x; idx < total;
         idx += (long)gridDim.x * blockDim.x) {
        long row = idx / Kpad;
        int k = (int)(idx - row * Kpad);
        float v = (k < Kin) ? in[row * (long)Kin + k] : 0.0f;
        __nv_bfloat16 hi = __float2bfloat16(v);
        __nv_bfloat16 lo = __float2bfloat16(v - __bfloat162float(hi));
        __nv_bfloat16* o = out + row * (long)(3 * Kpad);
        o[k] = hi;
        if (ASIDE) {
            o[Kpad + k] = lo;
            o[2 * Kpad + k] = hi;
        } else {
            o[Kpad + k] = hi;
            o[2 * Kpad + k] = lo;
        }
    }
}

// transpose + 3-plane split (B-side order)
__global__ void tsplit3(const float* __restrict__ in, __nv_bfloat16* __restrict__ out,
                        int R, int Cc, int Rpad, long sIn, long sOut) {
    __shared__ float t[32][33];
    const int b = blockIdx.z;
    const float* ip = in + (long)b * sIn;
    __nv_bfloat16* op = out + (long)b * sOut;
    const int r0 = blockIdx.x * 32, c0 = blockIdx.y * 32;
    const int tx = threadIdx.x, ty = threadIdx.y;    // 32x8
    for (int i = ty; i < 32; i += 8) {
        int r = r0 + i, c = c0 + tx;
        t[i][tx] = (r < R && c < Cc) ? ip[(long)r * Cc + c] : 0.0f;
    }
    __syncthreads();
    for (int i = ty; i < 32; i += 8) {
        int c = c0 + i, r = r0 + tx;
        if (c < Cc && r < Rpad) {
            float v = t[tx][i];
            __nv_bfloat16 hi = __float2bfloat16(v);
            __nv_bfloat16 lo = __float2bfloat16(v - __bfloat162float(hi));
            __nv_bfloat16* o = op + (long)c * (3 * Rpad);
            o[r] = hi;
            o[Rpad + r] = hi;
            o[2 * Rpad + r] = lo;
        }
    }
}

// ---------------- fused softmax + 3-plane split (A-side order) ----------------
__inline__ __device__ float warpMax(float v) {
#pragma unroll
    for (int o = 16; o > 0; o >>= 1) v = fmaxf(v, __shfl_xor_sync(0xffffffffu, v, o));
    return v;
}
__inline__ __device__ float warpSum(float v) {
#pragma unroll
    for (int o = 16; o > 0; o >>= 1) v += __shfl_xor_sync(0xffffffffu, v, o);
    return v;
}
__global__ void softmax_split(const float* __restrict__ S, __nv_bfloat16* __restrict__ Pk) {
    const long row = blockIdx.x;           // b*CN + c
    const float4* p = (const float4*)(S + row * (long)TT);
    constexpr int NV = TT / 4;
    __shared__ float4 buf[NV];
    __shared__ float red[8];
    const int tid = threadIdx.x;           // 256
    const int wid = tid >> 5, lid = tid & 31;

    float m = -INFINITY;
    for (int i = tid; i < NV; i += 256) {
        float4 v = p[i];
        buf[i] = v;
        m = fmaxf(m, fmaxf(fmaxf(v.x, v.y), fmaxf(v.z, v.w)));
    }
    m = warpMax(m);
    if (lid == 0) red[wid] = m;
    __syncthreads();
    if (wid == 0) {
        float v = (lid < 8) ? red[lid] : -INFINITY;
        v = warpMax(v);
        if (lid == 0) red[0] = v;
    }
    __syncthreads();
    m = red[0];
    __syncthreads();

    float s = 0.0f;
    for (int i = tid; i < NV; i += 256) {
        float4 v = buf[i];
        v.x = __expf(v.x - m); v.y = __expf(v.y - m);
        v.z = __expf(v.z - m); v.w = __expf(v.w - m);
        buf[i] = v;
        s += v.x + v.y + v.z + v.w;
    }
    s = warpSum(s);
    if (lid == 0) red[wid] = s;
    __syncthreads();
    if (wid == 0) {
        float v = (lid < 8) ? red[lid] : 0.0f;
        v = warpSum(v);
        if (lid == 0) red[0] = v;
    }
    __syncthreads();
    const float inv = 1.0f / red[0];

    // write 3 planes [hi|lo|hi], zero-padded to T_PAD, packed as bf16x2
    __nv_bfloat16* o = Pk + row * (long)(3 * T_PAD);
    const float* bf = (const float*)buf;
    for (int idx = tid; idx < T_PAD / 2; idx += 256) {
        int i = idx * 2;
        float p0 = (i < TT) ? bf[i] * inv : 0.0f;
        float p1 = (i + 1 < TT) ? bf[i + 1] * inv : 0.0f;
        __nv_bfloat16 h0 = __float2bfloat16(p0), h1 = __float2bfloat16(p1);
        __nv_bfloat16 l0 = __float2bfloat16(p0 - __bfloat162float(h0));
        __nv_bfloat16 l1 = __float2bfloat16(p1 - __bfloat162float(h1));
        __nv_bfloat162 hp = __halves2bfloat162(h0, h1);
        __nv_bfloat162 lp = __halves2bfloat162(l0, l1);
        *(__nv_bfloat162*)(o + i) = hp;
        *(__nv_bfloat162*)(o + T_PAD + i) = lp;
        *(__nv_bfloat162*)(o + 2 * T_PAD + i) = hp;
    }
}

// ---------------- driver ----------------
extern "C" void kernel_launch(void* const* d_in, const int* in_sizes, int n_in,
                              void* d_out, int out_size) {
    const float* X  = (const float*)d_in[0];   // [B,T,XD]
    const float* H  = (const float*)d_in[1];   // [B,T,HD]
    const float* W1 = (const float*)d_in[2];   // [XD,HD]
    const float* W2 = (const float*)d_in[3];   // [CN,T]
    float* out = (float*)d_out;                // [B,CN,HD]

    float *Z, *Y, *S;
    __nv_bfloat16 *W2k, *Xt, *Zk, *W1t, *Yk, *Hk, *Pk, *Ht;
    cudaGetSymbolAddress((void**)&Z, g_Z);
    cudaGetSymbolAddress((void**)&Y, g_Y);
    cudaGetSymbolAddress((void**)&S, g_S);
    cudaGetSymbolAddress((void**)&W2k, g_W2k);
    cudaGetSymbolAddress((void**)&Xt, g_Xt);
    cudaGetSymbolAddress((void**)&Zk, g_Zk);
    cudaGetSymbolAddress((void**)&W1t, g_W1t);
    cudaGetSymbolAddress((void**)&Yk, g_Yk);
    cudaGetSymbolAddress((void**)&Hk, g_Hk);
    cudaGetSymbolAddress((void**)&Pk, g_Pk);
    cudaGetSymbolAddress((void**)&Ht, g_Ht);

    const int DSM128 = (128 + 128) * 40 * 2 * 3;   // 61440
    const int DSM96  = (128 + 96)  * 40 * 2 * 3;   // 53760
    static bool attr_set = false;
    if (!attr_set) {
        cudaFuncSetAttribute(gemm_ca<128>, cudaFuncAttributeMaxDynamicSharedMemorySize, DSM128);
        cudaFuncSetAttribute(gemm_ca<96>,  cudaFuncAttributeMaxDynamicSharedMemorySize, DSM96);
        attr_set = true;
    }

    const dim3 tb(32, 8);

    // prep: X^T split (B-side), W2 split (A-side)
    tsplit3<<<dim3(T_PAD / 32, XD / 32, BB), tb>>>(X, Xt, TT, XD, T_PAD,
                                                   (long)TT * XD, (long)XD * 3 * T_PAD);
    split3<true><<<1024, 256>>>(W2, W2k, CN, TT, T_PAD);

    // K1: Z[b] = W2 @ X[b]        M=345 N=96 K'=4224
    gemm_ca<96><<<dim3(1, 3, BB), 256, DSM96>>>(
        W2k, Xt, Z, CN, XD, 3 * T_PAD, 3 * T_PAD, 3 * T_PAD, XD,
        0L, (long)XD * 3 * T_PAD, (long)CN * XD, 1.0f);

    // prep: Z split (A-side), W1^T split (B-side)
    split3<true><<<1024, 256>>>(Z, Zk, (long)BB * CN, XD, XD_PAD);
    tsplit3<<<dim3(XD_PAD / 32, HD / 32, 1), tb>>>(W1, W1t, XD, HD, XD_PAD, 0L, 0L);

    // K2: Y[b] = SCALE * Z[b] @ W1    M=345 N=192 K'=384
    gemm_ca<96><<<dim3(2, 3, BB), 256, DSM96>>>(
        Zk, W1t, Y, CN, HD, 3 * XD_PAD, 3 * XD_PAD, 3 * XD_PAD, HD,
        (long)CN * 3 * XD_PAD, 0L, (long)CN * HD, SCALE_F);

    // prep: Y split (A-side), H split (B-side, K-major natural)
    split3<true><<<1024, 256>>>(Y, Yk, (long)BB * CN, HD, HD_PAD);
    split3<false><<<2048, 256>>>(H, Hk, (long)BB * TT, HD, HD_PAD);

    // K3: S[b] = Y[b] @ H[b]^T    M=345 N=1380 K'=576
    gemm_ca<128><<<dim3(11, 3, BB), 256, DSM128>>>(
        Yk, Hk, S, CN, TT, 3 * HD_PAD, 3 * HD_PAD, 3 * HD_PAD, TT,
        (long)CN * 3 * HD_PAD, (long)TT * 3 * HD_PAD, (long)CN * TT, 1.0f);

    // fused softmax + A-side 3-plane split -> Pk
    softmax_split<<<BB * CN, 256>>>(S, Pk);

    // prep: H^T split (B-side)
    tsplit3<<<dim3(T_PAD / 32, HD / 32, BB), tb>>>(H, Ht, TT, HD, T_PAD,
                                                   (long)TT * HD, (long)HD * 3 * T_PAD);

    // K5: out[b] = P[b] @ H[b]    M=345 N=192 K'=4224
    gemm_ca<96><<<dim3(2, 3, BB), 256, DSM96>>>(
        Pk, Ht, out, CN, HD, 3 * T_PAD, 3 * T_PAD, 3 * T_PAD, HD,
        (long)CN * 3 * T_PAD, (long)HD * 3 * T_PAD, (long)CN * HD, 1.0f);
}

// round 9
// speedup vs baseline: 2.7833x; 1.1454x over previous
#include <cuda_runtime.h>
#include <cuda_bf16.h>
#include <cstdint>
#include <math.h>

#define BB 64
#define TT 1380
#define XD 96
#define HD 192
#define CN 345

#define T_PAD 1408           // TT padded to mult of 128
#define XD_PAD 128
#define HD_PAD 192

#define SCALE_F (1.0f / (9.79795897113271f * 13.856406460551018f))

// ---------------- device scratch (allocation-free rule) ----------------
__device__ float g_S[(long)BB * CN * TT];

// bf16 3-plane K-concat buffers.  A-side order: [hi|lo|hi].  B-side order: [hi|hi|lo].
__device__ __align__(16) __nv_bfloat16 g_W2k[(long)CN * 3 * T_PAD];          // A-side
__device__ __align__(16) __nv_bfloat16 g_Xt [(long)BB * XD * 3 * T_PAD];     // B-side
__device__ __align__(16) __nv_bfloat16 g_Zk [(long)BB * CN * 3 * XD_PAD];    // A-side (pad cols stay zero-init)
__device__ __align__(16) __nv_bfloat16 g_W1t[(long)HD * 3 * XD_PAD];         // B-side
__device__ __align__(16) __nv_bfloat16 g_Yk [(long)BB * CN * 3 * HD_PAD];    // A-side
__device__ __align__(16) __nv_bfloat16 g_Hk [(long)BB * TT * 3 * HD_PAD];    // B-side
__device__ __align__(16) __nv_bfloat16 g_Pk [(long)BB * CN * 3 * T_PAD];     // A-side
__device__ __align__(16) __nv_bfloat16 g_Ht [(long)BB * HD * 3 * T_PAD];     // B-side

// ---------------- PTX helpers (sm_80-class, safe at compute_103) ----------------
__device__ __forceinline__ uint32_t smem_u32(const void* p) {
    uint32_t a;
    asm("{ .reg .u64 t; cvta.to.shared.u64 t, %1; cvt.u32.u64 %0, t; }" : "=r"(a) : "l"(p));
    return a;
}
__device__ __forceinline__ void ldm_x4(uint32_t addr, uint32_t* r) {
    asm volatile("ldmatrix.sync.aligned.m8n8.x4.shared.b16 {%0,%1,%2,%3}, [%4];"
                 : "=r"(r[0]), "=r"(r[1]), "=r"(r[2]), "=r"(r[3]) : "r"(addr));
}
__device__ __forceinline__ void mma16816(float* c, const uint32_t* a, const uint32_t* b) {
    asm volatile("mma.sync.aligned.m16n8k16.row.col.f32.bf16.bf16.f32 "
                 "{%0,%1,%2,%3}, {%4,%5,%6,%7}, {%8,%9}, {%0,%1,%2,%3};"
                 : "+f"(c[0]), "+f"(c[1]), "+f"(c[2]), "+f"(c[3])
                 : "r"(a[0]), "r"(a[1]), "r"(a[2]), "r"(a[3]), "r"(b[0]), "r"(b[1]));
}
__device__ __forceinline__ void cp16(uint32_t dst, const void* src, int sz) {
    asm volatile("cp.async.cg.shared.global [%0], [%1], 16, %2;" :: "r"(dst), "l"(src), "r"(sz));
}

// A-side split pair writer: planes [hi | lo | hi], plane stride = pl elements
__device__ __forceinline__ void wsplit2(__nv_bfloat16* o, int pl, float v0, float v1) {
    __nv_bfloat16 h0 = __float2bfloat16(v0), h1 = __float2bfloat16(v1);
    __nv_bfloat16 l0 = __float2bfloat16(v0 - __bfloat162float(h0));
    __nv_bfloat16 l1 = __float2bfloat16(v1 - __bfloat162float(h1));
    __nv_bfloat162 hp = __halves2bfloat162(h0, h1);
    __nv_bfloat162 lp = __halves2bfloat162(l0, l1);
    *(__nv_bfloat162*)(o) = hp;
    *(__nv_bfloat162*)(o + pl) = lp;
    *(__nv_bfloat162*)(o + 2 * pl) = hp;
}

// ---------------- cp.async 3-stage pipelined GEMM:  C[m,n] = alpha*sum_k A[m,k]*B[n,k] ----
// BM=128, BK=64. SPLIT=true: C is bf16 3-plane A-side buffer, ldc = plane size.
template <int BN, bool SPLIT>
__global__ void __launch_bounds__(256)
gemm_ca(const __nv_bfloat16* __restrict__ A, const __nv_bfloat16* __restrict__ B,
        void* __restrict__ Cv, int M, int N, int Kp, int lda, int ldb, int ldc,
        long sA, long sB, long sC, float alpha) {
    constexpr int BM = 128, BK = 64, STAGES = 3, PAD = 72;
    constexpr int WN = BN / 2, NP = WN / 16, NJ = WN / 8;
    constexpr int AE = BM * PAD, BE = BN * PAD, SE = AE + BE;
    constexpr int BCH = BN * 8;                 // B 16B-chunks per stage
    extern __shared__ __nv_bfloat16 sm[];

    const int tid = threadIdx.x;
    const int wid = tid >> 5, lane = tid & 31;
    const int wm = wid & 3, wn = wid >> 2;
    const int bz = blockIdx.z;
    const __nv_bfloat16* Ab = A + (long)bz * sA;
    const __nv_bfloat16* Bb = B + (long)bz * sB;
    const int m0 = blockIdx.y * BM, n0 = blockIdx.x * BN;

    float acc[2][NJ][4];
#pragma unroll
    for (int i = 0; i < 2; i++)
#pragma unroll
        for (int j = 0; j < NJ; j++)
#pragma unroll
            for (int q = 0; q < 4; q++) acc[i][j][q] = 0.0f;

    const int la16 = lane & 15, lhi = lane >> 4;
    const int bn = (lane & 7) + ((lane >> 4) & 1) * 8;
    const int bk = ((lane >> 3) & 1) * 8;

    auto load_stage = [&](int s, int kt) {
        __nv_bfloat16* as = sm + s * SE;
        __nv_bfloat16* bs = sm + s * SE + AE;
        const long k0 = (long)kt * BK;
#pragma unroll
        for (int i = 0; i < 4; i++) {               // A: 1024 chunks, 4/thread
            int c = tid + i * 256;
            int row = c >> 3, col = c & 7;
            long gr = m0 + row;
            int ok = gr < M;
            const __nv_bfloat16* gp = Ab + (ok ? gr : 0) * (long)lda + k0 + col * 8;
            cp16(smem_u32(as + row * PAD + col * 8), gp, ok ? 16 : 0);
        }
#pragma unroll
        for (int i = 0; i < BCH / 256; i++) {
            int c = tid + i * 256;
            int row = c >> 3, col = c & 7;
            long gr = n0 + row;
            int ok = gr < N;
            const __nv_bfloat16* gp = Bb + (ok ? gr : 0) * (long)ldb + k0 + col * 8;
            cp16(smem_u32(bs + row * PAD + col * 8), gp, ok ? 16 : 0);
        }
        asm volatile("cp.async.commit_group;");
    };

    auto compute = [&](int s) {
        __nv_bfloat16* as = sm + s * SE;
        __nv_bfloat16* bs = sm + s * SE + AE;
#pragma unroll
        for (int ks = 0; ks < 4; ks++) {
            uint32_t af[2][4], bf[NP][4];
#pragma unroll
            for (int mi = 0; mi < 2; mi++)
                ldm_x4(smem_u32(as + (wm * 32 + mi * 16 + la16) * PAD + ks * 16 + lhi * 8), af[mi]);
#pragma unroll
            for (int p = 0; p < NP; p++)
                ldm_x4(smem_u32(bs + (wn * WN + p * 16 + bn) * PAD + ks * 16 + bk), bf[p]);
#pragma unroll
            for (int mi = 0; mi < 2; mi++)
#pragma unroll
                for (int nj = 0; nj < NJ; nj++)
                    mma16816(acc[mi][nj], af[mi], bf[nj >> 1] + (nj & 1) * 2);
        }
    };

    const int nk = Kp / BK;
    load_stage(0, 0);
    load_stage(1, 1);

    for (int kt = 0; kt < nk; kt++) {
        // TAIL FIX: at kt==nk-1 the group carrying tile nk-1 is the newest
        // committed group; wait_group(1) would let it stay in flight. Drain all.
        if (kt + 1 == nk) asm volatile("cp.async.wait_group 0;");
        else              asm volatile("cp.async.wait_group %0;" :: "n"(STAGES - 2));
        __syncthreads();
        if (kt + STAGES - 1 < nk) load_stage((kt + STAGES - 1) % STAGES, kt + STAGES - 1);
        compute(kt % STAGES);
    }

    // epilogue
    const int gid = lane >> 2, tig = lane & 3;
#pragma unroll
    for (int mi = 0; mi < 2; mi++) {
#pragma unroll
        for (int nj = 0; nj < NJ; nj++) {
            int r = m0 + wm * 32 + mi * 16 + gid;
            int c = n0 + wn * WN + nj * 8 + tig * 2;
            if (c < N) {
                if constexpr (SPLIT) {
                    __nv_bfloat16* Cb = (__nv_bfloat16*)Cv + (long)bz * sC;
                    if (r < M)
                        wsplit2(Cb + (long)r * 3 * ldc + c, ldc,
                                acc[mi][nj][0] * alpha, acc[mi][nj][1] * alpha);
                    if (r + 8 < M)
                        wsplit2(Cb + (long)(r + 8) * 3 * ldc + c, ldc,
                                acc[mi][nj][2] * alpha, acc[mi][nj][3] * alpha);
                } else {
                    float* Cb = (float*)Cv + (long)bz * sC;
                    if (r < M) {
                        float2 v = make_float2(acc[mi][nj][0] * alpha, acc[mi][nj][1] * alpha);
                        *(float2*)&Cb[(long)r * ldc + c] = v;
                    }
                    if (r + 8 < M) {
                        float2 v = make_float2(acc[mi][nj][2] * alpha, acc[mi][nj][3] * alpha);
                        *(float2*)&Cb[(long)(r + 8) * ldc + c] = v;
                    }
                }
            }
        }
    }
}

// ---------------- vectorized converts ----------------
// float4 in -> 3 bf16 planes out. ASIDE: [hi|lo|hi]; else B-side [hi|hi|lo].
template <bool ASIDE>
__global__ void split3v(const float* __restrict__ in, __nv_bfloat16* __restrict__ out,
                        long rows, int Kin, int Kpad) {
    const int kq = Kpad >> 2;
    long total = rows * (long)kq;
    for (long idx = blockIdx.x * (long)blockDim.x + threadIdx.x; idx < total;
         idx += (long)gridDim.x * blockDim.x) {
        long row = idx / kq;
        int k = (int)(idx - row * kq) << 2;
        float4 v = make_float4(0.f, 0.f, 0.f, 0.f);
        if (k < Kin) v = *(const float4*)(in + row * (long)Kin + k);
        __nv_bfloat16 h0 = __float2bfloat16(v.x), h1 = __float2bfloat16(v.y);
        __nv_bfloat16 h2 = __float2bfloat16(v.z), h3 = __float2bfloat16(v.w);
        __nv_bfloat162 hp0 = __halves2bfloat162(h0, h1);
        __nv_bfloat162 hp1 = __halves2bfloat162(h2, h3);
        __nv_bfloat162 lp0 = __halves2bfloat162(
            __float2bfloat16(v.x - __bfloat162float(h0)),
            __float2bfloat16(v.y - __bfloat162float(h1)));
        __nv_bfloat162 lp1 = __halves2bfloat162(
            __float2bfloat16(v.z - __bfloat162float(h2)),
            __float2bfloat16(v.w - __bfloat162float(h3)));
        __nv_bfloat16* o = out + row * (long)(3 * Kpad) + k;
        *(__nv_bfloat162*)(o) = hp0;
        *(__nv_bfloat162*)(o + 2) = hp1;
        if (ASIDE) {
            *(__nv_bfloat162*)(o + Kpad) = lp0;     *(__nv_bfloat162*)(o + Kpad + 2) = lp1;
            *(__nv_bfloat162*)(o + 2 * Kpad) = hp0; *(__nv_bfloat162*)(o + 2 * Kpad + 2) = hp1;
        } else {
            *(__nv_bfloat162*)(o + Kpad) = hp0;     *(__nv_bfloat162*)(o + Kpad + 2) = hp1;
            *(__nv_bfloat162*)(o + 2 * Kpad) = lp0; *(__nv_bfloat162*)(o + 2 * Kpad + 2) = lp1;
        }
    }
}

// transpose + 3-plane split (B-side order), 64-row tiles, bf16x2 stores.
// Rpad must be a multiple of 64.
__global__ void tsplit3v(const float* __restrict__ in, __nv_bfloat16* __restrict__ out,
                         int R, int Cc, int Rpad, long sIn, long sOut) {
    __shared__ float t[64][33];
    const int b = blockIdx.z;
    const float* ip = in + (long)b * sIn;
    __nv_bfloat16* op = out + (long)b * sOut;
    const int r0 = blockIdx.x * 64, c0 = blockIdx.y * 32;
    const int tx = threadIdx.x, ty = threadIdx.y;    // 32x8
#pragma unroll
    for (int i = 0; i < 8; i++) {
        int r = r0 + ty + i * 8;
        int c = c0 + tx;
        t[ty + i * 8][tx] = (r < R && c < Cc) ? ip[(long)r * Cc + c] : 0.0f;
    }
    __syncthreads();
#pragma unroll
    for (int i = 0; i < 4; i++) {
        int c = c0 + ty + i * 8;
        if (c < Cc) {
            int rp = r0 + 2 * tx;
            float v0 = t[2 * tx][ty + i * 8];
            float v1 = t[2 * tx + 1][ty + i * 8];
            __nv_bfloat16 h0 = __float2bfloat16(v0), h1 = __float2bfloat16(v1);
            __nv_bfloat162 hp = __halves2bfloat162(h0, h1);
            __nv_bfloat162 lp = __halves2bfloat162(
                __float2bfloat16(v0 - __bfloat162float(h0)),
                __float2bfloat16(v1 - __bfloat162float(h1)));
            __nv_bfloat16* o = op + (long)c * (3 * Rpad) + rp;
            *(__nv_bfloat162*)(o) = hp;
            *(__nv_bfloat162*)(o + Rpad) = hp;
            *(__nv_bfloat162*)(o + 2 * Rpad) = lp;
        }
    }
}

// ---------------- fused softmax + 3-plane split (A-side order) ----------------
__inline__ __device__ float warpMax(float v) {
#pragma unroll
    for (int o = 16; o > 0; o >>= 1) v = fmaxf(v, __shfl_xor_sync(0xffffffffu, v, o));
    return v;
}
__inline__ __device__ float warpSum(float v) {
#pragma unroll
    for (int o = 16; o > 0; o >>= 1) v += __shfl_xor_sync(0xffffffffu, v, o);
    return v;
}
__global__ void softmax_split(const float* __restrict__ S, __nv_bfloat16* __restrict__ Pk) {
    const long row = blockIdx.x;           // b*CN + c
    const float4* p = (const float4*)(S + row * (long)TT);
    constexpr int NV = TT / 4;
    __shared__ float4 buf[NV];
    __shared__ float red[8];
    const int tid = threadIdx.x;           // 256
    const int wid = tid >> 5, lid = tid & 31;

    float m = -INFINITY;
    for (int i = tid; i < NV; i += 256) {
        float4 v = p[i];
        buf[i] = v;
        m = fmaxf(m, fmaxf(fmaxf(v.x, v.y), fmaxf(v.z, v.w)));
    }
    m = warpMax(m);
    if (lid == 0) red[wid] = m;
    __syncthreads();
    if (wid == 0) {
        float v = (lid < 8) ? red[lid] : -INFINITY;
        v = warpMax(v);
        if (lid == 0) red[0] = v;
    }
    __syncthreads();
    m = red[0];
    __syncthreads();

    float s = 0.0f;
    for (int i = tid; i < NV; i += 256) {
        float4 v = buf[i];
        v.x = __expf(v.x - m); v.y = __expf(v.y - m);
        v.z = __expf(v.z - m); v.w = __expf(v.w - m);
        buf[i] = v;
        s += v.x + v.y + v.z + v.w;
    }
    s = warpSum(s);
    if (lid == 0) red[wid] = s;
    __syncthreads();
    if (wid == 0) {
        float v = (lid < 8) ? red[lid] : 0.0f;
        v = warpSum(v);
        if (lid == 0) red[0] = v;
    }
    __syncthreads();
    const float inv = 1.0f / red[0];

    __nv_bfloat16* o = Pk + row * (long)(3 * T_PAD);
    const float* bf = (const float*)buf;
    for (int idx = tid; idx < T_PAD / 2; idx += 256) {
        int i = idx * 2;
        float p0 = (i < TT) ? bf[i] * inv : 0.0f;
        float p1 = (i + 1 < TT) ? bf[i + 1] * inv : 0.0f;
        __nv_bfloat16 h0 = __float2bfloat16(p0), h1 = __float2bfloat16(p1);
        __nv_bfloat16 l0 = __float2bfloat16(p0 - __bfloat162float(h0));
        __nv_bfloat16 l1 = __float2bfloat16(p1 - __bfloat162float(h1));
        __nv_bfloat162 hp = __halves2bfloat162(h0, h1);
        __nv_bfloat162 lp = __halves2bfloat162(l0, l1);
        *(__nv_bfloat162*)(o + i) = hp;
        *(__nv_bfloat162*)(o + T_PAD + i) = lp;
        *(__nv_bfloat162*)(o + 2 * T_PAD + i) = hp;
    }
}

// ---------------- driver ----------------
extern "C" void kernel_launch(void* const* d_in, const int* in_sizes, int n_in,
                              void* d_out, int out_size) {
    const float* X  = (const float*)d_in[0];   // [B,T,XD]
    const float* H  = (const float*)d_in[1];   // [B,T,HD]
    const float* W1 = (const float*)d_in[2];   // [XD,HD]
    const float* W2 = (const float*)d_in[3];   // [CN,T]
    float* out = (float*)d_out;                // [B,CN,HD]

    float* S;
    __nv_bfloat16 *W2k, *Xt, *Zk, *W1t, *Yk, *Hk, *Pk, *Ht;
    cudaGetSymbolAddress((void**)&S, g_S);
    cudaGetSymbolAddress((void**)&W2k, g_W2k);
    cudaGetSymbolAddress((void**)&Xt, g_Xt);
    cudaGetSymbolAddress((void**)&Zk, g_Zk);
    cudaGetSymbolAddress((void**)&W1t, g_W1t);
    cudaGetSymbolAddress((void**)&Yk, g_Yk);
    cudaGetSymbolAddress((void**)&Hk, g_Hk);
    cudaGetSymbolAddress((void**)&Pk, g_Pk);
    cudaGetSymbolAddress((void**)&Ht, g_Ht);

    const int DSM128 = (128 + 128) * 72 * 2 * 3;   // 110592
    const int DSM96  = (128 + 96)  * 72 * 2 * 3;   // 96768
    static bool attr_set = false;
    if (!attr_set) {
        cudaFuncSetAttribute(gemm_ca<128, false>, cudaFuncAttributeMaxDynamicSharedMemorySize, DSM128);
        cudaFuncSetAttribute(gemm_ca<96, false>,  cudaFuncAttributeMaxDynamicSharedMemorySize, DSM96);
        cudaFuncSetAttribute(gemm_ca<96, true>,   cudaFuncAttributeMaxDynamicSharedMemorySize, DSM96);
        attr_set = true;
    }

    const dim3 tb(32, 8);

    // prep: X^T split (B-side), W2 split (A-side)
    tsplit3v<<<dim3(T_PAD / 64, XD / 32, BB), tb>>>(X, Xt, TT, XD, T_PAD,
                                                    (long)TT * XD, (long)XD * 3 * T_PAD);
    split3v<true><<<480, 256>>>(W2, W2k, CN, TT, T_PAD);

    // K1: Zk[b] = split(W2 @ X[b])        M=345 N=96 K'=4224
    gemm_ca<96, true><<<dim3(1, 3, BB), 256, DSM96>>>(
        W2k, Xt, Zk, CN, XD, 3 * T_PAD, 3 * T_PAD, 3 * T_PAD, XD_PAD,
        0L, (long)XD * 3 * T_PAD, (long)CN * 3 * XD_PAD, 1.0f);

    // prep: W1^T split (B-side)
    tsplit3v<<<dim3(XD_PAD / 64, HD / 32, 1), tb>>>(W1, W1t, XD, HD, XD_PAD, 0L, 0L);

    // K2: Yk[b] = split(SCALE * Z[b] @ W1)    M=345 N=192 K'=384
    gemm_ca<96, true><<<dim3(2, 3, BB), 256, DSM96>>>(
        Zk, W1t, Yk, CN, HD, 3 * XD_PAD, 3 * XD_PAD, 3 * XD_PAD, HD_PAD,
        (long)CN * 3 * XD_PAD, 0L, (long)CN * 3 * HD_PAD, SCALE_F);

    // prep: H split (B-side, K-major natural)
    split3v<false><<<4096, 256>>>(H, Hk, (long)BB * TT, HD, HD_PAD);

    // K3: S[b] = Y[b] @ H[b]^T    M=345 N=1380 K'=576
    gemm_ca<128, false><<<dim3(11, 3, BB), 256, DSM128>>>(
        Yk, Hk, S, CN, TT, 3 * HD_PAD, 3 * HD_PAD, 3 * HD_PAD, TT,
        (long)CN * 3 * HD_PAD, (long)TT * 3 * HD_PAD, (long)CN * TT, 1.0f);

    // fused softmax + A-side 3-plane split -> Pk
    softmax_split<<<BB * CN, 256>>>(S, Pk);

    // prep: H^T split (B-side)
    tsplit3v<<<dim3(T_PAD / 64, HD / 32, BB), tb>>>(H, Ht, TT, HD, T_PAD,
                                                    (long)TT * HD, (long)HD * 3 * T_PAD);

    // K5: out[b] = P[b] @ H[b]    M=345 N=192 K'=4224
    gemm_ca<96, false><<<dim3(2, 3, BB), 256, DSM96>>>(
        Pk, Ht, out, CN, HD, 3 * T_PAD, 3 * T_PAD, 3 * T_PAD, HD,
        (long)CN * 3 * T_PAD, (long)HD * 3 * T_PAD, (long)CN * HD, 1.0f);
}

// round 11
// speedup vs baseline: 2.8861x; 1.0369x over previous
#include <cuda_runtime.h>
#include <cuda_bf16.h>
#include <cstdint>
#include <math.h>

#define BB 64
#define TT 1380
#define XD 96
#define HD 192
#define CN 345

#define T_PAD 1408           // TT padded to mult of 128
#define XD_PAD 128
#define HD_PAD 192

#define SCALE_F (1.0f / (9.79795897113271f * 13.856406460551018f))

// ---------------- device scratch (allocation-free rule) ----------------
__device__ float g_S[(long)BB * CN * TT];

// 2-plane bf16 buffers: physical layout [rows][ P0=hi | P1=lo ], row stride 2*Kpad.
// Logical 3-plane K-concat is reconstructed at load time:
//   A-side [hi|lo|hi]: phys_k = k>=2K ? k-2K : k
//   B-side [hi|hi|lo]: phys_k = k>=K  ? k-K  : k
__device__ __align__(16) __nv_bfloat16 g_W2k[(long)CN * 2 * T_PAD];
__device__ __align__(16) __nv_bfloat16 g_Xt [(long)BB * XD * 2 * T_PAD];
__device__ __align__(16) __nv_bfloat16 g_Zk [(long)BB * CN * 2 * XD_PAD];   // pad cols stay zero-init
__device__ __align__(16) __nv_bfloat16 g_W1t[(long)HD * 2 * XD_PAD];
__device__ __align__(16) __nv_bfloat16 g_Yk [(long)BB * CN * 2 * HD_PAD];
__device__ __align__(16) __nv_bfloat16 g_Hk [(long)BB * TT * 2 * HD_PAD];
__device__ __align__(16) __nv_bfloat16 g_Pk [(long)BB * CN * 2 * T_PAD];
__device__ __align__(16) __nv_bfloat16 g_Ht [(long)BB * HD * 2 * T_PAD];

// split-K fp32 partials
__device__ float g_Zp[2L * BB * CN * XD];
__device__ float g_Op[2L * BB * CN * HD];

// ---------------- PTX helpers (sm_80-class, safe at compute_103) ----------------
__device__ __forceinline__ uint32_t smem_u32(const void* p) {
    uint32_t a;
    asm("{ .reg .u64 t; cvta.to.shared.u64 t, %1; cvt.u32.u64 %0, t; }" : "=r"(a) : "l"(p));
    return a;
}
__device__ __forceinline__ void ldm_x4(uint32_t addr, uint32_t* r) {
    asm volatile("ldmatrix.sync.aligned.m8n8.x4.shared.b16 {%0,%1,%2,%3}, [%4];"
                 : "=r"(r[0]), "=r"(r[1]), "=r"(r[2]), "=r"(r[3]) : "r"(addr));
}
__device__ __forceinline__ void mma16816(float* c, const uint32_t* a, const uint32_t* b) {
    asm volatile("mma.sync.aligned.m16n8k16.row.col.f32.bf16.bf16.f32 "
                 "{%0,%1,%2,%3}, {%4,%5,%6,%7}, {%8,%9}, {%0,%1,%2,%3};"
                 : "+f"(c[0]), "+f"(c[1]), "+f"(c[2]), "+f"(c[3])
                 : "r"(a[0]), "r"(a[1]), "r"(a[2]), "r"(a[3]), "r"(b[0]), "r"(b[1]));
}
__device__ __forceinline__ void cp16(uint32_t dst, const void* src, int sz) {
    asm volatile("cp.async.cg.shared.global [%0], [%1], 16, %2;" :: "r"(dst), "l"(src), "r"(sz));
}

// 2-plane split pair writer: P0=hi, P1=lo, plane stride pl
__device__ __forceinline__ void wsplit2(__nv_bfloat16* o, int pl, float v0, float v1) {
    __nv_bfloat16 h0 = __float2bfloat16(v0), h1 = __float2bfloat16(v1);
    __nv_bfloat16 l0 = __float2bfloat16(v0 - __bfloat162float(h0));
    __nv_bfloat16 l1 = __float2bfloat16(v1 - __bfloat162float(h1));
    *(__nv_bfloat162*)(o) = __halves2bfloat162(h0, h1);
    *(__nv_bfloat162*)(o + pl) = __halves2bfloat162(l0, l1);
}

// ---------------- cp.async 3-stage pipelined GEMM ----------------
//   C[m,n] = alpha * sum_{k<Kp} A[m, mapA(kBase+k)] * B[n, mapB(kBase+k)]
// BM=128, BK=64. SPLITOUT: C = 2-plane bf16 buffer (ldc = plane size).
// Split-K: blockIdx.x = nt + nTiles*ks; kBase = ks*Kp; fp32 C offset ks*sK.
template <int BN, bool SPLITOUT>
__global__ void __launch_bounds__(256)
gemm_ca(const __nv_bfloat16* __restrict__ A, const __nv_bfloat16* __restrict__ B,
        void* __restrict__ Cv, int M, int N, int Kp, int ldaP, int ldbP, int ldc,
        long sA, long sB, long sC, float alpha,
        int KpadA, int KpadB, int nTiles, long sK) {
    constexpr int BM = 128, BK = 64, STAGES = 3, PAD = 72;
    constexpr int WN = BN / 2, NP = WN / 16, NJ = WN / 8;
    constexpr int AE = BM * PAD, BE = BN * PAD, SE = AE + BE;
    constexpr int BCH = BN * 8;
    extern __shared__ __nv_bfloat16 sm[];

    const int tid = threadIdx.x;
    const int wid = tid >> 5, lane = tid & 31;
    const int wm = wid & 3, wn = wid >> 2;
    const int bz = blockIdx.z;
    const int nt = blockIdx.x % nTiles;
    const int ks = blockIdx.x / nTiles;
    const long kBase = (long)ks * Kp;
    const __nv_bfloat16* Ab = A + (long)bz * sA;
    const __nv_bfloat16* Bb = B + (long)bz * sB;
    const int m0 = blockIdx.y * BM, n0 = nt * BN;

    float acc[2][NJ][4];
#pragma unroll
    for (int i = 0; i < 2; i++)
#pragma unroll
        for (int j = 0; j < NJ; j++)
#pragma unroll
            for (int q = 0; q < 4; q++) acc[i][j][q] = 0.0f;

    const int la16 = lane & 15, lhi = lane >> 4;
    const int bn = (lane & 7) + ((lane >> 4) & 1) * 8;
    const int bk = ((lane >> 3) & 1) * 8;

    auto load_stage = [&](int s, int kt) {
        __nv_bfloat16* as = sm + s * SE;
        __nv_bfloat16* bs = sm + s * SE + AE;
        const long k0 = kBase + (long)kt * BK;
        const long kA = (k0 >= 2L * KpadA) ? k0 - 2L * KpadA : k0;   // A: [hi|lo|hi]
        const long kB = (k0 >= (long)KpadB) ? k0 - KpadB : k0;       // B: [hi|hi|lo]
#pragma unroll
        for (int i = 0; i < 4; i++) {
            int c = tid + i * 256;
            int row = c >> 3, col = c & 7;
            long gr = m0 + row;
            int ok = gr < M;
            const __nv_bfloat16* gp = Ab + (ok ? gr : 0) * (long)ldaP + kA + col * 8;
            cp16(smem_u32(as + row * PAD + col * 8), gp, ok ? 16 : 0);
        }
#pragma unroll
        for (int i = 0; i < BCH / 256; i++) {
            int c = tid + i * 256;
            int row = c >> 3, col = c & 7;
            long gr = n0 + row;
            int ok = gr < N;
            const __nv_bfloat16* gp = Bb + (ok ? gr : 0) * (long)ldbP + kB + col * 8;
            cp16(smem_u32(bs + row * PAD + col * 8), gp, ok ? 16 : 0);
        }
        asm volatile("cp.async.commit_group;");
    };

    auto compute = [&](int s) {
        __nv_bfloat16* as = sm + s * SE;
        __nv_bfloat16* bs = sm + s * SE + AE;
#pragma unroll
        for (int ksx = 0; ksx < 4; ksx++) {
            uint32_t af[2][4], bf[NP][4];
#pragma unroll
            for (int mi = 0; mi < 2; mi++)
                ldm_x4(smem_u32(as + (wm * 32 + mi * 16 + la16) * PAD + ksx * 16 + lhi * 8), af[mi]);
#pragma unroll
            for (int p = 0; p < NP; p++)
                ldm_x4(smem_u32(bs + (wn * WN + p * 16 + bn) * PAD + ksx * 16 + bk), bf[p]);
#pragma unroll
            for (int mi = 0; mi < 2; mi++)
#pragma unroll
                for (int nj = 0; nj < NJ; nj++)
                    mma16816(acc[mi][nj], af[mi], bf[nj >> 1] + (nj & 1) * 2);
        }
    };

    const int nk = Kp / BK;
    load_stage(0, 0);
    load_stage(1, 1);

    for (int kt = 0; kt < nk; kt++) {
        // tail: the group carrying tile nk-1 is the newest committed — drain all.
        if (kt + 1 == nk) asm volatile("cp.async.wait_group 0;");
        else              asm volatile("cp.async.wait_group %0;" :: "n"(STAGES - 2));
        __syncthreads();
        if (kt + STAGES - 1 < nk) load_stage((kt + STAGES - 1) % STAGES, kt + STAGES - 1);
        compute(kt % STAGES);
    }

    // epilogue
    const int gid = lane >> 2, tig = lane & 3;
#pragma unroll
    for (int mi = 0; mi < 2; mi++) {
#pragma unroll
        for (int nj = 0; nj < NJ; nj++) {
            int r = m0 + wm * 32 + mi * 16 + gid;
            int c = n0 + wn * WN + nj * 8 + tig * 2;
            if (c < N) {
                if constexpr (SPLITOUT) {
                    __nv_bfloat16* Cb = (__nv_bfloat16*)Cv + (long)bz * sC;
                    if (r < M)
                        wsplit2(Cb + (long)r * 2 * ldc + c, ldc,
                                acc[mi][nj][0] * alpha, acc[mi][nj][1] * alpha);
                    if (r + 8 < M)
                        wsplit2(Cb + (long)(r + 8) * 2 * ldc + c, ldc,
                                acc[mi][nj][2] * alpha, acc[mi][nj][3] * alpha);
                } else {
                    float* Cb = (float*)Cv + (long)bz * sC + (long)ks * sK;
                    if (r < M) {
                        float2 v = make_float2(acc[mi][nj][0] * alpha, acc[mi][nj][1] * alpha);
                        *(float2*)&Cb[(long)r * ldc + c] = v;
                    }
                    if (r + 8 < M) {
                        float2 v = make_float2(acc[mi][nj][2] * alpha, acc[mi][nj][3] * alpha);
                        *(float2*)&Cb[(long)(r + 8) * ldc + c] = v;
                    }
                }
            }
        }
    }
}

// ---------------- split-K combiners ----------------
// Zp[2][rows][N] fp32 -> out 2-plane bf16 [rows][2*Kpad]
__global__ void combine_split(const float* __restrict__ Zp, __nv_bfloat16* __restrict__ out,
                              long rows, int N, int Kpad, long sK) {
    const int nh = N >> 1;
    long total = rows * nh;
    for (long idx = blockIdx.x * (long)blockDim.x + threadIdx.x; idx < total;
         idx += (long)gridDim.x * blockDim.x) {
        long row = idx / nh;
        int n = (int)(idx - row * nh) * 2;
        const float* z = Zp + row * N + n;
        float v0 = z[0] + z[sK], v1 = z[1] + z[sK + 1];
        wsplit2(out + row * (long)(2 * Kpad) + n, Kpad, v0, v1);
    }
}
// Op[2][n] fp32 -> out[n] fp32
__global__ void combine_out(const float* __restrict__ Op, float* __restrict__ out, long n4, long sK4) {
    const float4* a = (const float4*)Op;
    float4* o = (float4*)out;
    for (long i = blockIdx.x * (long)blockDim.x + threadIdx.x; i < n4;
         i += (long)gridDim.x * blockDim.x) {
        float4 x = a[i], y = a[i + sK4];
        o[i] = make_float4(x.x + y.x, x.y + y.y, x.z + y.z, x.w + y.w);
    }
}

// ---------------- vectorized converts (2-plane: P0=hi, P1=lo) ----------------
__global__ void split3v(const float* __restrict__ in, __nv_bfloat16* __restrict__ out,
                        long rows, int Kin, int Kpad) {
    const int kq = Kpad >> 2;
    long total = rows * (long)kq;
    for (long idx = blockIdx.x * (long)blockDim.x + threadIdx.x; idx < total;
         idx += (long)gridDim.x * blockDim.x) {
        long row = idx / kq;
        int k = (int)(idx - row * kq) << 2;
        float4 v = make_float4(0.f, 0.f, 0.f, 0.f);
        if (k < Kin) v = *(const float4*)(in + row * (long)Kin + k);
        __nv_bfloat16 h0 = __float2bfloat16(v.x), h1 = __float2bfloat16(v.y);
        __nv_bfloat16 h2 = __float2bfloat16(v.z), h3 = __float2bfloat16(v.w);
        __nv_bfloat16* o = out + row * (long)(2 * Kpad) + k;
        *(__nv_bfloat162*)(o) = __halves2bfloat162(h0, h1);
        *(__nv_bfloat162*)(o + 2) = __halves2bfloat162(h2, h3);
        *(__nv_bfloat162*)(o + Kpad) = __halves2bfloat162(
            __float2bfloat16(v.x - __bfloat162float(h0)),
            __float2bfloat16(v.y - __bfloat162float(h1)));
        *(__nv_bfloat162*)(o + Kpad + 2) = __halves2bfloat162(
            __float2bfloat16(v.z - __bfloat162float(h2)),
            __float2bfloat16(v.w - __bfloat162float(h3)));
    }
}

// transpose + 2-plane split, 64-row tiles, bf16x2 stores. Rpad mult of 64.
__global__ void tsplit3v(const float* __restrict__ in, __nv_bfloat16* __restrict__ out,
                         int R, int Cc, int Rpad, long sIn, long sOut) {
    __shared__ float t[64][33];
    const int b = blockIdx.z;
    const float* ip = in + (long)b * sIn;
    __nv_bfloat16* op = out + (long)b * sOut;
    const int r0 = blockIdx.x * 64, c0 = blockIdx.y * 32;
    const int tx = threadIdx.x, ty = threadIdx.y;    // 32x8
#pragma unroll
    for (int i = 0; i < 8; i++) {
        int r = r0 + ty + i * 8;
        int c = c0 + tx;
        t[ty + i * 8][tx] = (r < R && c < Cc) ? ip[(long)r * Cc + c] : 0.0f;
    }
    __syncthreads();
#pragma unroll
    for (int i = 0; i < 4; i++) {
        int c = c0 + ty + i * 8;
        if (c < Cc) {
            int rp = r0 + 2 * tx;
            float v0 = t[2 * tx][ty + i * 8];
            float v1 = t[2 * tx + 1][ty + i * 8];
            wsplit2(op + (long)c * (2 * Rpad) + rp, Rpad, v0, v1);
        }
    }
}

// ---------------- fused softmax + 2-plane split ----------------
__inline__ __device__ float warpMax(float v) {
#pragma unroll
    for (int o = 16; o > 0; o >>= 1) v = fmaxf(v, __shfl_xor_sync(0xffffffffu, v, o));
    return v;
}
__inline__ __device__ float warpSum(float v) {
#pragma unroll
    for (int o = 16; o > 0; o >>= 1) v += __shfl_xor_sync(0xffffffffu, v, o);
    return v;
}
__global__ void softmax_split(const float* __restrict__ S, __nv_bfloat16* __restrict__ Pk) {
    const long row = blockIdx.x;
    const float4* p = (const float4*)(S + row * (long)TT);
    constexpr int NV = TT / 4;
    __shared__ float4 buf[NV];
    __shared__ float red[8];
    const int tid = threadIdx.x;
    const int wid = tid >> 5, lid = tid & 31;

    float m = -INFINITY;
    for (int i = tid; i < NV; i += 256) {
        float4 v = p[i];
        buf[i] = v;
        m = fmaxf(m, fmaxf(fmaxf(v.x, v.y), fmaxf(v.z, v.w)));
    }
    m = warpMax(m);
    if (lid == 0) red[wid] = m;
    __syncthreads();
    if (wid == 0) {
        float v = (lid < 8) ? red[lid] : -INFINITY;
        v = warpMax(v);
        if (lid == 0) red[0] = v;
    }
    __syncthreads();
    m = red[0];
    __syncthreads();

    float s = 0.0f;
    for (int i = tid; i < NV; i += 256) {
        float4 v = buf[i];
        v.x = __expf(v.x - m); v.y = __expf(v.y - m);
        v.z = __expf(v.z - m); v.w = __expf(v.w - m);
        buf[i] = v;
        s += v.x + v.y + v.z + v.w;
    }
    s = warpSum(s);
    if (lid == 0) red[wid] = s;
    __syncthreads();
    if (wid == 0) {
        float v = (lid < 8) ? red[lid] : 0.0f;
        v = warpSum(v);
        if (lid == 0) red[0] = v;
    }
    __syncthreads();
    const float inv = 1.0f / red[0];

    __nv_bfloat16* o = Pk + row * (long)(2 * T_PAD);
    const float* bf = (const float*)buf;
    for (int idx = tid; idx < T_PAD / 2; idx += 256) {
        int i = idx * 2;
        float p0 = (i < TT) ? bf[i] * inv : 0.0f;
        float p1 = (i + 1 < TT) ? bf[i + 1] * inv : 0.0f;
        wsplit2(o + i, T_PAD, p0, p1);
    }
}

// ---------------- driver ----------------
extern "C" void kernel_launch(void* const* d_in, const int* in_sizes, int n_in,
                              void* d_out, int out_size) {
    const float* X  = (const float*)d_in[0];   // [B,T,XD]
    const float* H  = (const float*)d_in[1];   // [B,T,HD]
    const float* W1 = (const float*)d_in[2];   // [XD,HD]
    const float* W2 = (const float*)d_in[3];   // [CN,T]
    float* out = (float*)d_out;                // [B,CN,HD]

    float *S, *Zp, *Op;
    __nv_bfloat16 *W2k, *Xt, *Zk, *W1t, *Yk, *Hk, *Pk, *Ht;
    cudaGetSymbolAddress((void**)&S, g_S);
    cudaGetSymbolAddress((void**)&Zp, g_Zp);
    cudaGetSymbolAddress((void**)&Op, g_Op);
    cudaGetSymbolAddress((void**)&W2k, g_W2k);
    cudaGetSymbolAddress((void**)&Xt, g_Xt);
    cudaGetSymbolAddress((void**)&Zk, g_Zk);
    cudaGetSymbolAddress((void**)&W1t, g_W1t);
    cudaGetSymbolAddress((void**)&Yk, g_Yk);
    cudaGetSymbolAddress((void**)&Hk, g_Hk);
    cudaGetSymbolAddress((void**)&Pk, g_Pk);
    cudaGetSymbolAddress((void**)&Ht, g_Ht);

    const int DSM128 = (128 + 128) * 72 * 2 * 3;   // 110592
    const int DSM96  = (128 + 96)  * 72 * 2 * 3;   // 96768
    static bool attr_set = false;
    if (!attr_set) {
        cudaFuncSetAttribute(gemm_ca<128, false>, cudaFuncAttributeMaxDynamicSharedMemorySize, DSM128);
        cudaFuncSetAttribute(gemm_ca<96, false>,  cudaFuncAttributeMaxDynamicSharedMemorySize, DSM96);
        cudaFuncSetAttribute(gemm_ca<96, true>,   cudaFuncAttributeMaxDynamicSharedMemorySize, DSM96);
        attr_set = true;
    }

    const dim3 tb(32, 8);

    // prep: X^T split, W2 split
    tsplit3v<<<dim3(T_PAD / 64, XD / 32, BB), tb>>>(X, Xt, TT, XD, T_PAD,
                                                    (long)TT * XD, (long)XD * 2 * T_PAD);
    split3v<<<480, 256>>>(W2, W2k, CN, TT, T_PAD);

    // K1 (split-K x2): Zp[ks][b] = partial(W2 @ X[b])   M=345 N=96, K'=4224 -> 2x2112
    gemm_ca<96, false><<<dim3(2, 3, BB), 256, DSM96>>>(
        W2k, Xt, Zp, CN, XD, 2112, 2 * T_PAD, 2 * T_PAD, XD,
        0L, (long)XD * 2 * T_PAD, (long)CN * XD, 1.0f,
        T_PAD, T_PAD, 1, (long)BB * CN * XD);
    combine_split<<<2048, 256>>>(Zp, Zk, (long)BB * CN, XD, XD_PAD, (long)BB * CN * XD);

    // prep: W1^T split
    tsplit3v<<<dim3(XD_PAD / 64, HD / 32, 1), tb>>>(W1, W1t, XD, HD, XD_PAD, 0L, 0L);

    // K2: Yk[b] = split(SCALE * Z[b] @ W1)    M=345 N=192, K'=384
    gemm_ca<96, true><<<dim3(2, 3, BB), 256, DSM96>>>(
        Zk, W1t, Yk, CN, HD, 3 * XD_PAD, 2 * XD_PAD, 2 * XD_PAD, HD_PAD,
        (long)CN * 2 * XD_PAD, 0L, (long)CN * 2 * HD_PAD, SCALE_F,
        XD_PAD, XD_PAD, 2, 0L);

    // prep: H split (K-major natural)
    split3v<<<4096, 256>>>(H, Hk, (long)BB * TT, HD, HD_PAD);

    // K3: S[b] = Y[b] @ H[b]^T    M=345 N=1380, K'=576
    gemm_ca<128, false><<<dim3(11, 3, BB), 256, DSM128>>>(
        Yk, Hk, S, CN, TT, 3 * HD_PAD, 2 * HD_PAD, 2 * HD_PAD, TT,
        (long)CN * 2 * HD_PAD, (long)TT * 2 * HD_PAD, (long)CN * TT, 1.0f,
        HD_PAD, HD_PAD, 11, 0L);

    // fused softmax + 2-plane split -> Pk
    softmax_split<<<BB * CN, 256>>>(S, Pk);

    // prep: H^T split
    tsplit3v<<<dim3(T_PAD / 64, HD / 32, BB), tb>>>(H, Ht, TT, HD, T_PAD,
                                                    (long)TT * HD, (long)HD * 2 * T_PAD);

    // K5 (split-K x2): Op[ks][b] = partial(P[b] @ H[b])   M=345 N=192, K'=4224 -> 2x2112
    gemm_ca<96, false><<<dim3(4, 3, BB), 256, DSM96>>>(
        Pk, Ht, Op, CN, HD, 2112, 2 * T_PAD, 2 * T_PAD, HD,
        (long)CN * 2 * T_PAD, (long)HD * 2 * T_PAD, (long)CN * HD, 1.0f,
        T_PAD, T_PAD, 2, (long)BB * CN * HD);
    combine_out<<<2048, 256>>>(Op, out, ((long)BB * CN * HD) / 4, ((long)BB * CN * HD) / 4);
}

// round 14
// speedup vs baseline: 2.9667x; 1.0279x over previous
#include <cuda_runtime.h>
#include <cuda_bf16.h>
#include <cstdint>
#include <math.h>

#define BB 64
#define TT 1380
#define XD 96
#define HD 192
#define CN 345

#define T_PAD 1408           // TT padded to mult of 128
#define XD_PAD 128
#define HD_PAD 192

#define SCALE_F (1.0f / (9.79795897113271f * 13.856406460551018f))

// ---------------- device scratch (allocation-free rule) ----------------
__device__ float g_S[(long)BB * CN * TT];

// 2-plane bf16 buffers: physical layout [rows][ P0=hi | P1=lo ], row stride 2*Kpad.
// Logical 3-plane K-concat reconstructed at load time:
//   A-side [hi|lo|hi]: phys_k = k>=2K ? k-2K : k
//   B-side [hi|hi|lo]: phys_k = k>=K  ? k-K  : k
__device__ __align__(16) __nv_bfloat16 g_W2k[(long)CN * 2 * T_PAD];
__device__ __align__(16) __nv_bfloat16 g_Xt [(long)BB * XD * 2 * T_PAD];
__device__ __align__(16) __nv_bfloat16 g_Zk [(long)BB * CN * 2 * XD_PAD];   // pad cols stay zero-init
__device__ __align__(16) __nv_bfloat16 g_W1t[(long)HD * 2 * XD_PAD];
__device__ __align__(16) __nv_bfloat16 g_Yk [(long)BB * CN * 2 * HD_PAD];
__device__ __align__(16) __nv_bfloat16 g_Hk [(long)BB * TT * 2 * HD_PAD];
__device__ __align__(16) __nv_bfloat16 g_Pk [(long)BB * CN * 2 * T_PAD];
__device__ __align__(16) __nv_bfloat16 g_Ht [(long)BB * HD * 2 * T_PAD];

// split-K fp32 partials
__device__ float g_Zp[2L * BB * CN * XD];
__device__ float g_Op[2L * BB * CN * HD];

// ---------------- PTX helpers ----------------
__device__ __forceinline__ uint32_t smem_u32(const void* p) {
    uint32_t a;
    asm("{ .reg .u64 t; cvta.to.shared.u64 t, %1; cvt.u32.u64 %0, t; }" : "=r"(a) : "l"(p));
    return a;
}
__device__ __forceinline__ void ldm_x4(uint32_t addr, uint32_t* r) {
    asm volatile("ldmatrix.sync.aligned.m8n8.x4.shared.b16 {%0,%1,%2,%3}, [%4];"
                 : "=r"(r[0]), "=r"(r[1]), "=r"(r[2]), "=r"(r[3]) : "r"(addr));
}
__device__ __forceinline__ void mma16816(float* c, const uint32_t* a, const uint32_t* b) {
    asm volatile("mma.sync.aligned.m16n8k16.row.col.f32.bf16.bf16.f32 "
                 "{%0,%1,%2,%3}, {%4,%5,%6,%7}, {%8,%9}, {%0,%1,%2,%3};"
                 : "+f"(c[0]), "+f"(c[1]), "+f"(c[2]), "+f"(c[3])
                 : "r"(a[0]), "r"(a[1]), "r"(a[2]), "r"(a[3]), "r"(b[0]), "r"(b[1]));
}
__device__ __forceinline__ void cp16(uint32_t dst, const void* src, int sz) {
    asm volatile("cp.async.cg.shared.global [%0], [%1], 16, %2;" :: "r"(dst), "l"(src), "r"(sz));
}

// 2-plane split pair writer: P0=hi, P1=lo, plane stride pl
__device__ __forceinline__ void wsplit2(__nv_bfloat16* o, int pl, float v0, float v1) {
    __nv_bfloat16 h0 = __float2bfloat16(v0), h1 = __float2bfloat16(v1);
    __nv_bfloat16 l0 = __float2bfloat16(v0 - __bfloat162float(h0));
    __nv_bfloat16 l1 = __float2bfloat16(v1 - __bfloat162float(h1));
    *(__nv_bfloat162*)(o) = __halves2bfloat162(h0, h1);
    *(__nv_bfloat162*)(o + pl) = __halves2bfloat162(l0, l1);
}

// ---------------- cp.async 3-stage pipelined GEMM ----------------
// C[m,n] = alpha * sum_{k<Kp} A[m, mapA(kBase+k)] * B[n, mapB(kBase+k)]
// OCC: blocks-per-SM hint (2 for BN=96, 1 for BN=128).
template <int BN, bool SPLITOUT, int OCC>
__global__ void __launch_bounds__(256, OCC)
gemm_ca(const __nv_bfloat16* __restrict__ A, const __nv_bfloat16* __restrict__ B,
        void* __restrict__ Cv, int M, int N, int Kp, int ldaP, int ldbP, int ldc,
        long sA, long sB, long sC, float alpha,
        int KpadA, int KpadB, int nTiles, long sK) {
    constexpr int BM = 128, BK = 64, STAGES = 3, PAD = 72;
    constexpr int WN = BN / 2, NP = WN / 16, NJ = WN / 8;
    constexpr int AE = BM * PAD, BE = BN * PAD, SE = AE + BE;
    constexpr int BCH = BN * 8;
    extern __shared__ __nv_bfloat16 sm[];

    const int tid = threadIdx.x;
    const int wid = tid >> 5, lane = tid & 31;
    const int wm = wid & 3, wn = wid >> 2;
    const int bz = blockIdx.z;
    const int nt = blockIdx.x % nTiles;
    const int ks = blockIdx.x / nTiles;
    const long kBase = (long)ks * Kp;
    const __nv_bfloat16* Ab = A + (long)bz * sA;
    const __nv_bfloat16* Bb = B + (long)bz * sB;
    const int m0 = blockIdx.y * BM, n0 = nt * BN;

    float acc[2][NJ][4];
#pragma unroll
    for (int i = 0; i < 2; i++)
#pragma unroll
        for (int j = 0; j < NJ; j++)
#pragma unroll
            for (int q = 0; q < 4; q++) acc[i][j][q] = 0.0f;

    const int la16 = lane & 15, lhi = lane >> 4;
    const int bn = (lane & 7) + ((lane >> 4) & 1) * 8;
    const int bk = ((lane >> 3) & 1) * 8;

    auto load_stage = [&](int s, int kt) {
        __nv_bfloat16* as = sm + s * SE;
        __nv_bfloat16* bs = sm + s * SE + AE;
        const long k0 = kBase + (long)kt * BK;
        const long kA = (k0 >= 2L * KpadA) ? k0 - 2L * KpadA : k0;   // A: [hi|lo|hi]
        const long kB = (k0 >= (long)KpadB) ? k0 - KpadB : k0;       // B: [hi|hi|lo]
#pragma unroll
        for (int i = 0; i < 4; i++) {
            int c = tid + i * 256;
            int row = c >> 3, col = c & 7;
            long gr = m0 + row;
            int ok = gr < M;
            const __nv_bfloat16* gp = Ab + (ok ? gr : 0) * (long)ldaP + kA + col * 8;
            cp16(smem_u32(as + row * PAD + col * 8), gp, ok ? 16 : 0);
        }
#pragma unroll
        for (int i = 0; i < BCH / 256; i++) {
            int c = tid + i * 256;
            int row = c >> 3, col = c & 7;
            long gr = n0 + row;
            int ok = gr < N;
            const __nv_bfloat16* gp = Bb + (ok ? gr : 0) * (long)ldbP + kB + col * 8;
            cp16(smem_u32(bs + row * PAD + col * 8), gp, ok ? 16 : 0);
        }
        asm volatile("cp.async.commit_group;");
    };

    auto compute = [&](int s) {
        __nv_bfloat16* as = sm + s * SE;
        __nv_bfloat16* bs = sm + s * SE + AE;
#pragma unroll
        for (int ksx = 0; ksx < 4; ksx++) {
            uint32_t af[2][4], bf[NP][4];
#pragma unroll
            for (int mi = 0; mi < 2; mi++)
                ldm_x4(smem_u32(as + (wm * 32 + mi * 16 + la16) * PAD + ksx * 16 + lhi * 8), af[mi]);
#pragma unroll
            for (int p = 0; p < NP; p++)
                ldm_x4(smem_u32(bs + (wn * WN + p * 16 + bn) * PAD + ksx * 16 + bk), bf[p]);
#pragma unroll
            for (int mi = 0; mi < 2; mi++)
#pragma unroll
                for (int nj = 0; nj < NJ; nj++)
                    mma16816(acc[mi][nj], af[mi], bf[nj >> 1] + (nj & 1) * 2);
        }
    };

    const int nk = Kp / BK;
    load_stage(0, 0);
    load_stage(1, 1);

    for (int kt = 0; kt < nk; kt++) {
        // tail: the group carrying tile nk-1 is the newest committed — drain all.
        if (kt + 1 == nk) asm volatile("cp.async.wait_group 0;");
        else              asm volatile("cp.async.wait_group %0;" :: "n"(STAGES - 2));
        __syncthreads();
        if (kt + STAGES - 1 < nk) load_stage((kt + STAGES - 1) % STAGES, kt + STAGES - 1);
        compute(kt % STAGES);
    }

    // epilogue
    const int gid = lane >> 2, tig = lane & 3;
#pragma unroll
    for (int mi = 0; mi < 2; mi++) {
#pragma unroll
        for (int nj = 0; nj < NJ; nj++) {
            int r = m0 + wm * 32 + mi * 16 + gid;
            int c = n0 + wn * WN + nj * 8 + tig * 2;
            if (c < N) {
                if constexpr (SPLITOUT) {
                    __nv_bfloat16* Cb = (__nv_bfloat16*)Cv + (long)bz * sC;
                    if (r < M)
                        wsplit2(Cb + (long)r * 2 * ldc + c, ldc,
                                acc[mi][nj][0] * alpha, acc[mi][nj][1] * alpha);
                    if (r + 8 < M)
                        wsplit2(Cb + (long)(r + 8) * 2 * ldc + c, ldc,
                                acc[mi][nj][2] * alpha, acc[mi][nj][3] * alpha);
                } else {
                    float* Cb = (float*)Cv + (long)bz * sC + (long)ks * sK;
                    if (r < M) {
                        float2 v = make_float2(acc[mi][nj][0] * alpha, acc[mi][nj][1] * alpha);
                        *(float2*)&Cb[(long)r * ldc + c] = v;
                    }
                    if (r + 8 < M) {
                        float2 v = make_float2(acc[mi][nj][2] * alpha, acc[mi][nj][3] * alpha);
                        *(float2*)&Cb[(long)(r + 8) * ldc + c] = v;
                    }
                }
            }
        }
    }
}

// ---------------- split-K combiners ----------------
__global__ void combine_split(const float* __restrict__ Zp, __nv_bfloat16* __restrict__ out,
                              long rows, int N, int Kpad, long sK) {
    const int nh = N >> 1;
    long total = rows * nh;
    for (long idx = blockIdx.x * (long)blockDim.x + threadIdx.x; idx < total;
         idx += (long)gridDim.x * blockDim.x) {
        long row = idx / nh;
        int n = (int)(idx - row * nh) * 2;
        const float* z = Zp + row * N + n;
        float v0 = z[0] + z[sK], v1 = z[1] + z[sK + 1];
        wsplit2(out + row * (long)(2 * Kpad) + n, Kpad, v0, v1);
    }
}
__global__ void combine_out(const float* __restrict__ Op, float* __restrict__ out, long n4, long sK4) {
    const float4* a = (const float4*)Op;
    float4* o = (float4*)out;
    for (long i = blockIdx.x * (long)blockDim.x + threadIdx.x; i < n4;
         i += (long)gridDim.x * blockDim.x) {
        float4 x = a[i], y = a[i + sK4];
        o[i] = make_float4(x.x + y.x, x.y + y.y, x.z + y.z, x.w + y.w);
    }
}

// ---------------- vectorized converts (2-plane: P0=hi, P1=lo) ----------------
__global__ void split3v(const float* __restrict__ in, __nv_bfloat16* __restrict__ out,
                        long rows, int Kin, int Kpad) {
    const int kq = Kpad >> 2;
    long total = rows * (long)kq;
    for (long idx = blockIdx.x * (long)blockDim.x + threadIdx.x; idx < total;
         idx += (long)gridDim.x * blockDim.x) {
        long row = idx / kq;
        int k = (int)(idx - row * kq) << 2;
        float4 v = make_float4(0.f, 0.f, 0.f, 0.f);
        if (k < Kin) v = *(const float4*)(in + row * (long)Kin + k);
        __nv_bfloat16 h0 = __float2bfloat16(v.x), h1 = __float2bfloat16(v.y);
        __nv_bfloat16 h2 = __float2bfloat16(v.z), h3 = __float2bfloat16(v.w);
        __nv_bfloat16* o = out + row * (long)(2 * Kpad) + k;
        *(__nv_bfloat162*)(o) = __halves2bfloat162(h0, h1);
        *(__nv_bfloat162*)(o + 2) = __halves2bfloat162(h2, h3);
        *(__nv_bfloat162*)(o + Kpad) = __halves2bfloat162(
            __float2bfloat16(v.x - __bfloat162float(h0)),
            __float2bfloat16(v.y - __bfloat162float(h1)));
        *(__nv_bfloat162*)(o + Kpad + 2) = __halves2bfloat162(
            __float2bfloat16(v.z - __bfloat162float(h2)),
            __float2bfloat16(v.w - __bfloat162float(h3)));
    }
}

// transpose + 2-plane split, 64-row tiles, bf16x2 stores. Rpad mult of 64.
__global__ void tsplit3v(const float* __restrict__ in, __nv_bfloat16* __restrict__ out,
                         int R, int Cc, int Rpad, long sIn, long sOut) {
    __shared__ float t[64][33];
    const int b = blockIdx.z;
    const float* ip = in + (long)b * sIn;
    __nv_bfloat16* op = out + (long)b * sOut;
    const int r0 = blockIdx.x * 64, c0 = blockIdx.y * 32;
    const int tx = threadIdx.x, ty = threadIdx.y;    // 32x8
#pragma unroll
    for (int i = 0; i < 8; i++) {
        int r = r0 + ty + i * 8;
        int c = c0 + tx;
        t[ty + i * 8][tx] = (r < R && c < Cc) ? ip[(long)r * Cc + c] : 0.0f;
    }
    __syncthreads();
#pragma unroll
    for (int i = 0; i < 4; i++) {
        int c = c0 + ty + i * 8;
        if (c < Cc) {
            int rp = r0 + 2 * tx;
            float v0 = t[2 * tx][ty + i * 8];
            float v1 = t[2 * tx + 1][ty + i * 8];
            wsplit2(op + (long)c * (2 * Rpad) + rp, Rpad, v0, v1);
        }
    }
}

// ---------------- fused softmax + 2-plane split ----------------
__inline__ __device__ float warpMax(float v) {
#pragma unroll
    for (int o = 16; o > 0; o >>= 1) v = fmaxf(v, __shfl_xor_sync(0xffffffffu, v, o));
    return v;
}
__inline__ __device__ float warpSum(float v) {
#pragma unroll
    for (int o = 16; o > 0; o >>= 1) v += __shfl_xor_sync(0xffffffffu, v, o);
    return v;
}
__global__ void softmax_split(const float* __restrict__ S, __nv_bfloat16* __restrict__ Pk) {
    const long row = blockIdx.x;
    const float4* p = (const float4*)(S + row * (long)TT);
    constexpr int NV = TT / 4;
    __shared__ float4 buf[NV];
    __shared__ float red[8];
    const int tid = threadIdx.x;
    const int wid = tid >> 5, lid = tid & 31;

    float m = -INFINITY;
    for (int i = tid; i < NV; i += 256) {
        float4 v = p[i];
        buf[i] = v;
        m = fmaxf(m, fmaxf(fmaxf(v.x, v.y), fmaxf(v.z, v.w)));
    }
    m = warpMax(m);
    if (lid == 0) red[wid] = m;
    __syncthreads();
    if (wid == 0) {
        float v = (lid < 8) ? red[lid] : -INFINITY;
        v = warpMax(v);
        if (lid == 0) red[0] = v;
    }
    __syncthreads();
    m = red[0];
    __syncthreads();

    float s = 0.0f;
    for (int i = tid; i < NV; i += 256) {
        float4 v = buf[i];
        v.x = __expf(v.x - m); v.y = __expf(v.y - m);
        v.z = __expf(v.z - m); v.w = __expf(v.w - m);
        buf[i] = v;
        s += v.x + v.y + v.z + v.w;
    }
    s = warpSum(s);
    if (lid == 0) red[wid] = s;
    __syncthreads();
    if (wid == 0) {
        float v = (lid < 8) ? red[lid] : 0.0f;
        v = warpSum(v);
        if (lid == 0) red[0] = v;
    }
    __syncthreads();
    const float inv = 1.0f / red[0];

    __nv_bfloat16* o = Pk + row * (long)(2 * T_PAD);
    const float* bf = (const float*)buf;
    for (int idx = tid; idx < T_PAD / 2; idx += 256) {
        int i = idx * 2;
        float p0 = (i < TT) ? bf[i] * inv : 0.0f;
        float p1 = (i + 1 < TT) ? bf[i + 1] * inv : 0.0f;
        wsplit2(o + i, T_PAD, p0, p1);
    }
}

// ---------------- driver ----------------
extern "C" void kernel_launch(void* const* d_in, const int* in_sizes, int n_in,
                              void* d_out, int out_size) {
    const float* X  = (const float*)d_in[0];   // [B,T,XD]
    const float* H  = (const float*)d_in[1];   // [B,T,HD]
    const float* W1 = (const float*)d_in[2];   // [XD,HD]
    const float* W2 = (const float*)d_in[3];   // [CN,T]
    float* out = (float*)d_out;                // [B,CN,HD]

    float *S, *Zp, *Op;
    __nv_bfloat16 *W2k, *Xt, *Zk, *W1t, *Yk, *Hk, *Pk, *Ht;
    cudaGetSymbolAddress((void**)&S, g_S);
    cudaGetSymbolAddress((void**)&Zp, g_Zp);
    cudaGetSymbolAddress((void**)&Op, g_Op);
    cudaGetSymbolAddress((void**)&W2k, g_W2k);
    cudaGetSymbolAddress((void**)&Xt, g_Xt);
    cudaGetSymbolAddress((void**)&Zk, g_Zk);
    cudaGetSymbolAddress((void**)&W1t, g_W1t);
    cudaGetSymbolAddress((void**)&Yk, g_Yk);
    cudaGetSymbolAddress((void**)&Hk, g_Hk);
    cudaGetSymbolAddress((void**)&Pk, g_Pk);
    cudaGetSymbolAddress((void**)&Ht, g_Ht);

    const int DSM128 = (128 + 128) * 72 * 2 * 3;   // 110592
    const int DSM96  = (128 + 96)  * 72 * 2 * 3;   // 96768
    static cudaStream_t sB = nullptr;
    static cudaEvent_t eRoot, eW1, eHk, eHt;
    if (!sB) {
        cudaFuncSetAttribute((const void*)gemm_ca<128, false, 1>, cudaFuncAttributeMaxDynamicSharedMemorySize, DSM128);
        cudaFuncSetAttribute((const void*)gemm_ca<96, false, 2>,  cudaFuncAttributeMaxDynamicSharedMemorySize, DSM96);
        cudaFuncSetAttribute((const void*)gemm_ca<96, true, 2>,   cudaFuncAttributeMaxDynamicSharedMemorySize, DSM96);
        cudaStreamCreateWithFlags(&sB, cudaStreamNonBlocking);
        cudaEventCreateWithFlags(&eRoot, cudaEventDisableTiming);
        cudaEventCreateWithFlags(&eW1, cudaEventDisableTiming);
        cudaEventCreateWithFlags(&eHk, cudaEventDisableTiming);
        cudaEventCreateWithFlags(&eHt, cudaEventDisableTiming);
    }

    const dim3 tb(32, 8);

    // fork stream B off the main stream
    cudaEventRecord(eRoot, 0);
    cudaStreamWaitEvent(sB, eRoot, 0);

    // --- stream B: input-only preps (H / W1 derived) ---
    tsplit3v<<<dim3(XD_PAD / 64, HD / 32, 1), tb, 0, sB>>>(W1, W1t, XD, HD, XD_PAD, 0L, 0L);
    cudaEventRecord(eW1, sB);
    split3v<<<4096, 256, 0, sB>>>(H, Hk, (long)BB * TT, HD, HD_PAD);
    cudaEventRecord(eHk, sB);
    tsplit3v<<<dim3(T_PAD / 64, HD / 32, BB), tb, 0, sB>>>(H, Ht, TT, HD, T_PAD,
                                                           (long)TT * HD, (long)HD * 2 * T_PAD);
    cudaEventRecord(eHt, sB);

    // --- main stream ---
    tsplit3v<<<dim3(T_PAD / 64, XD / 32, BB), tb>>>(X, Xt, TT, XD, T_PAD,
                                                    (long)TT * XD, (long)XD * 2 * T_PAD);
    split3v<<<480, 256>>>(W2, W2k, CN, TT, T_PAD);

    // K1 (split-K x2): Zp[ks][b] = partial(W2 @ X[b])   M=345 N=96, K'=4224 -> 2x2112
    gemm_ca<96, false, 2><<<dim3(2, 3, BB), 256, DSM96>>>(
        W2k, Xt, Zp, CN, XD, 2112, 2 * T_PAD, 2 * T_PAD, XD,
        0L, (long)XD * 2 * T_PAD, (long)CN * XD, 1.0f,
        T_PAD, T_PAD, 1, (long)BB * CN * XD);
    combine_split<<<2048, 256>>>(Zp, Zk, (long)BB * CN, XD, XD_PAD, (long)BB * CN * XD);

    // K2: Yk[b] = split(SCALE * Z[b] @ W1)    M=345 N=192, K'=384
    cudaStreamWaitEvent(0, eW1, 0);
    gemm_ca<96, true, 2><<<dim3(2, 3, BB), 256, DSM96>>>(
        Zk, W1t, Yk, CN, HD, 3 * XD_PAD, 2 * XD_PAD, 2 * XD_PAD, HD_PAD,
        (long)CN * 2 * XD_PAD, 0L, (long)CN * 2 * HD_PAD, SCALE_F,
        XD_PAD, XD_PAD, 2, 0L);

    // K3: S[b] = Y[b] @ H[b]^T    M=345 N=1380, K'=576
    cudaStreamWaitEvent(0, eHk, 0);
    gemm_ca<128, false, 1><<<dim3(11, 3, BB), 256, DSM128>>>(
        Yk, Hk, S, CN, TT, 3 * HD_PAD, 2 * HD_PAD, 2 * HD_PAD, TT,
        (long)CN * 2 * HD_PAD, (long)TT * 2 * HD_PAD, (long)CN * TT, 1.0f,
        HD_PAD, HD_PAD, 11, 0L);

    // fused softmax + 2-plane split -> Pk
    softmax_split<<<BB * CN, 256>>>(S, Pk);

    // K5 (split-K x2): Op[ks][b] = partial(P[b] @ H[b])   M=345 N=192, K'=4224 -> 2x2112
    cudaStreamWaitEvent(0, eHt, 0);
    gemm_ca<96, false, 2><<<dim3(4, 3, BB), 256, DSM96>>>(
        Pk, Ht, Op, CN, HD, 2112, 2 * T_PAD, 2 * T_PAD, HD,
        (long)CN * 2 * T_PAD, (long)HD * 2 * T_PAD, (long)CN * HD, 1.0f,
        T_PAD, T_PAD, 2, (long)BB * CN * HD);
    combine_out<<<2048, 256>>>(Op, out, ((long)BB * CN * HD) / 4, ((long)BB * CN * HD) / 4);
}

// round 15
// speedup vs baseline: 3.1076x; 1.0475x over previous
#include <cuda_runtime.h>
#include <cuda_bf16.h>
#include <cstdint>
#include <math.h>

#define BB 64
#define TT 1380
#define XD 96
#define HD 192
#define CN 345

#define T_PAD 1408           // TT padded to mult of 128
#define XD_PAD 128
#define HD_PAD 192

#define SCALE_F (1.0f / (9.79795897113271f * 13.856406460551018f))

// ---------------- device scratch (allocation-free rule) ----------------
__device__ float g_S[(long)BB * CN * TT];

// 2-plane bf16 buffers: physical layout [rows][ P0=hi | P1=lo ], row stride 2*Kpad.
// Logical 3-plane K-concat reconstructed at load time:
//   A-side [hi|lo|hi]: phys_k = k>=2K ? k-2K : k
//   B-side [hi|hi|lo]: phys_k = k>=K  ? k-K  : k
__device__ __align__(16) __nv_bfloat16 g_W2k[(long)CN * 2 * T_PAD];
__device__ __align__(16) __nv_bfloat16 g_Xt [(long)BB * XD * 2 * T_PAD];
__device__ __align__(16) __nv_bfloat16 g_Zk [(long)BB * CN * 2 * XD_PAD];   // pad cols stay zero-init
__device__ __align__(16) __nv_bfloat16 g_W1t[(long)HD * 2 * XD_PAD];
__device__ __align__(16) __nv_bfloat16 g_Yk [(long)BB * CN * 2 * HD_PAD];
__device__ __align__(16) __nv_bfloat16 g_Hk [(long)BB * TT * 2 * HD_PAD];
__device__ __align__(16) __nv_bfloat16 g_Pk [(long)BB * CN * 2 * T_PAD];
__device__ __align__(16) __nv_bfloat16 g_Ht [(long)BB * HD * 2 * T_PAD];

// split-K fp32 partials
__device__ float g_Zp[3L * BB * CN * XD];
__device__ float g_Op[2L * BB * CN * HD];

// ---------------- PTX helpers ----------------
__device__ __forceinline__ uint32_t smem_u32(const void* p) {
    uint32_t a;
    asm("{ .reg .u64 t; cvta.to.shared.u64 t, %1; cvt.u32.u64 %0, t; }" : "=r"(a) : "l"(p));
    return a;
}
__device__ __forceinline__ void ldm_x4(uint32_t addr, uint32_t* r) {
    asm volatile("ldmatrix.sync.aligned.m8n8.x4.shared.b16 {%0,%1,%2,%3}, [%4];"
                 : "=r"(r[0]), "=r"(r[1]), "=r"(r[2]), "=r"(r[3]) : "r"(addr));
}
__device__ __forceinline__ void mma16816(float* c, const uint32_t* a, const uint32_t* b) {
    asm volatile("mma.sync.aligned.m16n8k16.row.col.f32.bf16.bf16.f32 "
                 "{%0,%1,%2,%3}, {%4,%5,%6,%7}, {%8,%9}, {%0,%1,%2,%3};"
                 : "+f"(c[0]), "+f"(c[1]), "+f"(c[2]), "+f"(c[3])
                 : "r"(a[0]), "r"(a[1]), "r"(a[2]), "r"(a[3]), "r"(b[0]), "r"(b[1]));
}
__device__ __forceinline__ void cp16(uint32_t dst, const void* src, int sz) {
    asm volatile("cp.async.cg.shared.global [%0], [%1], 16, %2;" :: "r"(dst), "l"(src), "r"(sz));
}

// 2-plane split pair writer: P0=hi, P1=lo, plane stride pl
__device__ __forceinline__ void wsplit2(__nv_bfloat16* o, int pl, float v0, float v1) {
    __nv_bfloat16 h0 = __float2bfloat16(v0), h1 = __float2bfloat16(v1);
    __nv_bfloat16 l0 = __float2bfloat16(v0 - __bfloat162float(h0));
    __nv_bfloat16 l1 = __float2bfloat16(v1 - __bfloat162float(h1));
    *(__nv_bfloat162*)(o) = __halves2bfloat162(h0, h1);
    *(__nv_bfloat162*)(o + pl) = __halves2bfloat162(l0, l1);
}

// ---------------- cp.async 3-stage pipelined GEMM ----------------
// C[m,n] = alpha * sum_{k<Kp} A[m, mapA(kBase+k)] * B[n, mapB(kBase+k)]
template <int BN, bool SPLITOUT, int OCC>
__global__ void __launch_bounds__(256, OCC)
gemm_ca(const __nv_bfloat16* __restrict__ A, const __nv_bfloat16* __restrict__ B,
        void* __restrict__ Cv, int M, int N, int Kp, int ldaP, int ldbP, int ldc,
        long sA, long sB, long sC, float alpha,
        int KpadA, int KpadB, int nTiles, long sK) {
    constexpr int BM = 128, BK = 64, STAGES = 3, PAD = 72;
    constexpr int WN = BN / 2, NP = WN / 16, NJ = WN / 8;
    constexpr int AE = BM * PAD, BE = BN * PAD, SE = AE + BE;
    constexpr int BCH = BN * 8;
    extern __shared__ __nv_bfloat16 sm[];

    const int tid = threadIdx.x;
    const int wid = tid >> 5, lane = tid & 31;
    const int wm = wid & 3, wn = wid >> 2;
    const int bz = blockIdx.z;
    const int nt = blockIdx.x % nTiles;
    const int ks = blockIdx.x / nTiles;
    const long kBase = (long)ks * Kp;
    const __nv_bfloat16* Ab = A + (long)bz * sA;
    const __nv_bfloat16* Bb = B + (long)bz * sB;
    const int m0 = blockIdx.y * BM, n0 = nt * BN;

    float acc[2][NJ][4];
#pragma unroll
    for (int i = 0; i < 2; i++)
#pragma unroll
        for (int j = 0; j < NJ; j++)
#pragma unroll
            for (int q = 0; q < 4; q++) acc[i][j][q] = 0.0f;

    const int la16 = lane & 15, lhi = lane >> 4;
    const int bn = (lane & 7) + ((lane >> 4) & 1) * 8;
    const int bk = ((lane >> 3) & 1) * 8;

    auto load_stage = [&](int s, int kt) {
        __nv_bfloat16* as = sm + s * SE;
        __nv_bfloat16* bs = sm + s * SE + AE;
        const long k0 = kBase + (long)kt * BK;
        const long kA = (k0 >= 2L * KpadA) ? k0 - 2L * KpadA : k0;   // A: [hi|lo|hi]
        const long kB = (k0 >= (long)KpadB) ? k0 - KpadB : k0;       // B: [hi|hi|lo]
#pragma unroll
        for (int i = 0; i < 4; i++) {
            int c = tid + i * 256;
            int row = c >> 3, col = c & 7;
            long gr = m0 + row;
            int ok = gr < M;
            const __nv_bfloat16* gp = Ab + (ok ? gr : 0) * (long)ldaP + kA + col * 8;
            cp16(smem_u32(as + row * PAD + col * 8), gp, ok ? 16 : 0);
        }
#pragma unroll
        for (int i = 0; i < BCH / 256; i++) {
            int c = tid + i * 256;
            int row = c >> 3, col = c & 7;
            long gr = n0 + row;
            int ok = gr < N;
            const __nv_bfloat16* gp = Bb + (ok ? gr : 0) * (long)ldbP + kB + col * 8;
            cp16(smem_u32(bs + row * PAD + col * 8), gp, ok ? 16 : 0);
        }
        asm volatile("cp.async.commit_group;");
    };

    auto compute = [&](int s) {
        __nv_bfloat16* as = sm + s * SE;
        __nv_bfloat16* bs = sm + s * SE + AE;
#pragma unroll
        for (int ksx = 0; ksx < 4; ksx++) {
            uint32_t af[2][4], bf[NP][4];
#pragma unroll
            for (int mi = 0; mi < 2; mi++)
                ldm_x4(smem_u32(as + (wm * 32 + mi * 16 + la16) * PAD + ksx * 16 + lhi * 8), af[mi]);
#pragma unroll
            for (int p = 0; p < NP; p++)
                ldm_x4(smem_u32(bs + (wn * WN + p * 16 + bn) * PAD + ksx * 16 + bk), bf[p]);
#pragma unroll
            for (int mi = 0; mi < 2; mi++)
#pragma unroll
                for (int nj = 0; nj < NJ; nj++)
                    mma16816(acc[mi][nj], af[mi], bf[nj >> 1] + (nj & 1) * 2);
        }
    };

    const int nk = Kp / BK;
    load_stage(0, 0);
    load_stage(1, 1);

    for (int kt = 0; kt < nk; kt++) {
        // tail: the group carrying tile nk-1 is the newest committed — drain all.
        if (kt + 1 == nk) asm volatile("cp.async.wait_group 0;");
        else              asm volatile("cp.async.wait_group %0;" :: "n"(STAGES - 2));
        __syncthreads();
        if (kt + STAGES - 1 < nk) load_stage((kt + STAGES - 1) % STAGES, kt + STAGES - 1);
        compute(kt % STAGES);
    }

    // epilogue
    const int gid = lane >> 2, tig = lane & 3;
#pragma unroll
    for (int mi = 0; mi < 2; mi++) {
#pragma unroll
        for (int nj = 0; nj < NJ; nj++) {
            int r = m0 + wm * 32 + mi * 16 + gid;
            int c = n0 + wn * WN + nj * 8 + tig * 2;
            if (c < N) {
                if constexpr (SPLITOUT) {
                    __nv_bfloat16* Cb = (__nv_bfloat16*)Cv + (long)bz * sC;
                    if (r < M)
                        wsplit2(Cb + (long)r * 2 * ldc + c, ldc,
                                acc[mi][nj][0] * alpha, acc[mi][nj][1] * alpha);
                    if (r + 8 < M)
                        wsplit2(Cb + (long)(r + 8) * 2 * ldc + c, ldc,
                                acc[mi][nj][2] * alpha, acc[mi][nj][3] * alpha);
                } else {
                    float* Cb = (float*)Cv + (long)bz * sC + (long)ks * sK;
                    if (r < M) {
                        float2 v = make_float2(acc[mi][nj][0] * alpha, acc[mi][nj][1] * alpha);
                        *(float2*)&Cb[(long)r * ldc + c] = v;
                    }
                    if (r + 8 < M) {
                        float2 v = make_float2(acc[mi][nj][2] * alpha, acc[mi][nj][3] * alpha);
                        *(float2*)&Cb[(long)(r + 8) * ldc + c] = v;
                    }
                }
            }
        }
    }
}

// ---------------- split-K combiners ----------------
// Zp[nsplit][rows][N] fp32 -> out 2-plane bf16 [rows][2*Kpad]
__global__ void combine_split(const float* __restrict__ Zp, __nv_bfloat16* __restrict__ out,
                              long rows, int N, int Kpad, long sK, int nsplit) {
    const int nh = N >> 1;
    long total = rows * nh;
    for (long idx = blockIdx.x * (long)blockDim.x + threadIdx.x; idx < total;
         idx += (long)gridDim.x * blockDim.x) {
        long row = idx / nh;
        int n = (int)(idx - row * nh) * 2;
        const float* z = Zp + row * N + n;
        float v0 = 0.f, v1 = 0.f;
        for (int s = 0; s < nsplit; s++) {
            v0 += z[s * sK];
            v1 += z[s * sK + 1];
        }
        wsplit2(out + row * (long)(2 * Kpad) + n, Kpad, v0, v1);
    }
}
__global__ void combine_out(const float* __restrict__ Op, float* __restrict__ out, long n4, long sK4) {
    const float4* a = (const float4*)Op;
    float4* o = (float4*)out;
    for (long i = blockIdx.x * (long)blockDim.x + threadIdx.x; i < n4;
         i += (long)gridDim.x * blockDim.x) {
        float4 x = a[i], y = a[i + sK4];
        o[i] = make_float4(x.x + y.x, x.y + y.y, x.z + y.z, x.w + y.w);
    }
}

// ---------------- vectorized converts (2-plane: P0=hi, P1=lo) ----------------
__global__ void split3v(const float* __restrict__ in, __nv_bfloat16* __restrict__ out,
                        long rows, int Kin, int Kpad) {
    const int kq = Kpad >> 2;
    long total = rows * (long)kq;
    for (long idx = blockIdx.x * (long)blockDim.x + threadIdx.x; idx < total;
         idx += (long)gridDim.x * blockDim.x) {
        long row = idx / kq;
        int k = (int)(idx - row * kq) << 2;
        float4 v = make_float4(0.f, 0.f, 0.f, 0.f);
        if (k < Kin) v = *(const float4*)(in + row * (long)Kin + k);
        __nv_bfloat16 h0 = __float2bfloat16(v.x), h1 = __float2bfloat16(v.y);
        __nv_bfloat16 h2 = __float2bfloat16(v.z), h3 = __float2bfloat16(v.w);
        __nv_bfloat16* o = out + row * (long)(2 * Kpad) + k;
        *(__nv_bfloat162*)(o) = __halves2bfloat162(h0, h1);
        *(__nv_bfloat162*)(o + 2) = __halves2bfloat162(h2, h3);
        *(__nv_bfloat162*)(o + Kpad) = __halves2bfloat162(
            __float2bfloat16(v.x - __bfloat162float(h0)),
            __float2bfloat16(v.y - __bfloat162float(h1)));
        *(__nv_bfloat162*)(o + Kpad + 2) = __halves2bfloat162(
            __float2bfloat16(v.z - __bfloat162float(h2)),
            __float2bfloat16(v.w - __bfloat162float(h3)));
    }
}

// transpose + 2-plane split, 64-row tiles, bf16x2 stores. Rpad mult of 64.
__global__ void tsplit3v(const float* __restrict__ in, __nv_bfloat16* __restrict__ out,
                         int R, int Cc, int Rpad, long sIn, long sOut) {
    __shared__ float t[64][33];
    const int b = blockIdx.z;
    const float* ip = in + (long)b * sIn;
    __nv_bfloat16* op = out + (long)b * sOut;
    const int r0 = blockIdx.x * 64, c0 = blockIdx.y * 32;
    const int tx = threadIdx.x, ty = threadIdx.y;    // 32x8
#pragma unroll
    for (int i = 0; i < 8; i++) {
        int r = r0 + ty + i * 8;
        int c = c0 + tx;
        t[ty + i * 8][tx] = (r < R && c < Cc) ? ip[(long)r * Cc + c] : 0.0f;
    }
    __syncthreads();
#pragma unroll
    for (int i = 0; i < 4; i++) {
        int c = c0 + ty + i * 8;
        if (c < Cc) {
            int rp = r0 + 2 * tx;
            float v0 = t[2 * tx][ty + i * 8];
            float v1 = t[2 * tx + 1][ty + i * 8];
            wsplit2(op + (long)c * (2 * Rpad) + rp, Rpad, v0, v1);
        }
    }
}

// ---------------- fused softmax + 2-plane split ----------------
__inline__ __device__ float warpMax(float v) {
#pragma unroll
    for (int o = 16; o > 0; o >>= 1) v = fmaxf(v, __shfl_xor_sync(0xffffffffu, v, o));
    return v;
}
__inline__ __device__ float warpSum(float v) {
#pragma unroll
    for (int o = 16; o > 0; o >>= 1) v += __shfl_xor_sync(0xffffffffu, v, o);
    return v;
}
__global__ void softmax_split(const float* __restrict__ S, __nv_bfloat16* __restrict__ Pk) {
    const long row = blockIdx.x;
    const float4* p = (const float4*)(S + row * (long)TT);
    constexpr int NV = TT / 4;
    __shared__ float4 buf[NV];
    __shared__ float red[8];
    const int tid = threadIdx.x;
    const int wid = tid >> 5, lid = tid & 31;

    float m = -INFINITY;
    for (int i = tid; i < NV; i += 256) {
        float4 v = p[i];
        buf[i] = v;
        m = fmaxf(m, fmaxf(fmaxf(v.x, v.y), fmaxf(v.z, v.w)));
    }
    m = warpMax(m);
    if (lid == 0) red[wid] = m;
    __syncthreads();
    if (wid == 0) {
        float v = (lid < 8) ? red[lid] : -INFINITY;
        v = warpMax(v);
        if (lid == 0) red[0] = v;
    }
    __syncthreads();
    m = red[0];
    __syncthreads();

    float s = 0.0f;
    for (int i = tid; i < NV; i += 256) {
        float4 v = buf[i];
        v.x = __expf(v.x - m); v.y = __expf(v.y - m);
        v.z = __expf(v.z - m); v.w = __expf(v.w - m);
        buf[i] = v;
        s += v.x + v.y + v.z + v.w;
    }
    s = warpSum(s);
    if (lid == 0) red[wid] = s;
    __syncthreads();
    if (wid == 0) {
        float v = (lid < 8) ? red[lid] : 0.0f;
        v = warpSum(v);
        if (lid == 0) red[0] = v;
    }
    __syncthreads();
    const float inv = 1.0f / red[0];

    __nv_bfloat16* o = Pk + row * (long)(2 * T_PAD);
    const float* bf = (const float*)buf;
    for (int idx = tid; idx < T_PAD / 2; idx += 256) {
        int i = idx * 2;
        float p0 = (i < TT) ? bf[i] * inv : 0.0f;
        float p1 = (i + 1 < TT) ? bf[i + 1] * inv : 0.0f;
        wsplit2(o + i, T_PAD, p0, p1);
    }
}

// ---------------- driver ----------------
extern "C" void kernel_launch(void* const* d_in, const int* in_sizes, int n_in,
                              void* d_out, int out_size) {
    const float* X  = (const float*)d_in[0];   // [B,T,XD]
    const float* H  = (const float*)d_in[1];   // [B,T,HD]
    const float* W1 = (const float*)d_in[2];   // [XD,HD]
    const float* W2 = (const float*)d_in[3];   // [CN,T]
    float* out = (float*)d_out;                // [B,CN,HD]

    float *S, *Zp, *Op;
    __nv_bfloat16 *W2k, *Xt, *Zk, *W1t, *Yk, *Hk, *Pk, *Ht;
    cudaGetSymbolAddress((void**)&S, g_S);
    cudaGetSymbolAddress((void**)&Zp, g_Zp);
    cudaGetSymbolAddress((void**)&Op, g_Op);
    cudaGetSymbolAddress((void**)&W2k, g_W2k);
    cudaGetSymbolAddress((void**)&Xt, g_Xt);
    cudaGetSymbolAddress((void**)&Zk, g_Zk);
    cudaGetSymbolAddress((void**)&W1t, g_W1t);
    cudaGetSymbolAddress((void**)&Yk, g_Yk);
    cudaGetSymbolAddress((void**)&Hk, g_Hk);
    cudaGetSymbolAddress((void**)&Pk, g_Pk);
    cudaGetSymbolAddress((void**)&Ht, g_Ht);

    const int DSM96 = (128 + 96) * 72 * 2 * 3;   // 96768
    static cudaStream_t sB = nullptr;
    static cudaEvent_t eRoot, eW1, eHk, eHt;
    if (!sB) {
        cudaFuncSetAttribute((const void*)gemm_ca<96, false, 2>, cudaFuncAttributeMaxDynamicSharedMemorySize, DSM96);
        cudaFuncSetAttribute((const void*)gemm_ca<96, true, 2>,  cudaFuncAttributeMaxDynamicSharedMemorySize, DSM96);
        cudaStreamCreateWithFlags(&sB, cudaStreamNonBlocking);
        cudaEventCreateWithFlags(&eRoot, cudaEventDisableTiming);
        cudaEventCreateWithFlags(&eW1, cudaEventDisableTiming);
        cudaEventCreateWithFlags(&eHk, cudaEventDisableTiming);
        cudaEventCreateWithFlags(&eHt, cudaEventDisableTiming);
    }

    const dim3 tb(32, 8);

    // fork stream B off the main stream
    cudaEventRecord(eRoot, 0);
    cudaStreamWaitEvent(sB, eRoot, 0);

    // --- stream B: input-only preps (H / W1 derived) ---
    tsplit3v<<<dim3(XD_PAD / 64, HD / 32, 1), tb, 0, sB>>>(W1, W1t, XD, HD, XD_PAD, 0L, 0L);
    cudaEventRecord(eW1, sB);
    split3v<<<4096, 256, 0, sB>>>(H, Hk, (long)BB * TT, HD, HD_PAD);
    cudaEventRecord(eHk, sB);
    tsplit3v<<<dim3(T_PAD / 64, HD / 32, BB), tb, 0, sB>>>(H, Ht, TT, HD, T_PAD,
                                                           (long)TT * HD, (long)HD * 2 * T_PAD);
    cudaEventRecord(eHt, sB);

    // --- main stream ---
    tsplit3v<<<dim3(T_PAD / 64, XD / 32, BB), tb>>>(X, Xt, TT, XD, T_PAD,
                                                    (long)TT * XD, (long)XD * 2 * T_PAD);
    split3v<<<480, 256>>>(W2, W2k, CN, TT, T_PAD);

    // K1 (split-K x3, one logical plane per split): Zp[ks][b] = partial(W2 @ X[b])
    // M=345 N=96, K'=4224 -> 3x1408
    gemm_ca<96, false, 2><<<dim3(3, 3, BB), 256, DSM96>>>(
        W2k, Xt, Zp, CN, XD, 1408, 2 * T_PAD, 2 * T_PAD, XD,
        0L, (long)XD * 2 * T_PAD, (long)CN * XD, 1.0f,
        T_PAD, T_PAD, 1, (long)BB * CN * XD);
    combine_split<<<2048, 256>>>(Zp, Zk, (long)BB * CN, XD, XD_PAD, (long)BB * CN * XD, 3);

    // K2: Yk[b] = split(SCALE * Z[b] @ W1)    M=345 N=192, K'=384
    cudaStreamWaitEvent(0, eW1, 0);
    gemm_ca<96, true, 2><<<dim3(2, 3, BB), 256, DSM96>>>(
        Zk, W1t, Yk, CN, HD, 3 * XD_PAD, 2 * XD_PAD, 2 * XD_PAD, HD_PAD,
        (long)CN * 2 * XD_PAD, 0L, (long)CN * 2 * HD_PAD, SCALE_F,
        XD_PAD, XD_PAD, 2, 0L);

    // K3: S[b] = Y[b] @ H[b]^T    M=345 N=1380, K'=576   (BN=96 -> OCC=2, 15 tiles)
    cudaStreamWaitEvent(0, eHk, 0);
    gemm_ca<96, false, 2><<<dim3(15, 3, BB), 256, DSM96>>>(
        Yk, Hk, S, CN, TT, 3 * HD_PAD, 2 * HD_PAD, 2 * HD_PAD, TT,
        (long)CN * 2 * HD_PAD, (long)TT * 2 * HD_PAD, (long)CN * TT, 1.0f,
        HD_PAD, HD_PAD, 15, 0L);

    // fused softmax + 2-plane split -> Pk
    softmax_split<<<BB * CN, 256>>>(S, Pk);

    // K5 (split-K x2): Op[ks][b] = partial(P[b] @ H[b])   M=345 N=192, K'=4224 -> 2x2112
    cudaStreamWaitEvent(0, eHt, 0);
    gemm_ca<96, false, 2><<<dim3(4, 3, BB), 256, DSM96>>>(
        Pk, Ht, Op, CN, HD, 2112, 2 * T_PAD, 2 * T_PAD, HD,
        (long)CN * 2 * T_PAD, (long)HD * 2 * T_PAD, (long)CN * HD, 1.0f,
        T_PAD, T_PAD, 2, (long)BB * CN * HD);
    combine_out<<<2048, 256>>>(Op, out, ((long)BB * CN * HD) / 4, ((long)BB * CN * HD) / 4);
}